// round 2
// baseline (speedup 1.0000x reference)
#include <cuda_runtime.h>
#include <math.h>

#define BATCH 16
#define NPTS  16384
#define BNTOT (BATCH*NPTS)
#define NTILE (BNTOT/256)   // 1024 column tiles

typedef unsigned long long ull;

// ---------------- packed f32x2 helpers --------------------------------------
__device__ __forceinline__ ull pack2(float lo, float hi) {
    ull r; asm("mov.b64 %0, {%1, %2};" : "=l"(r) : "f"(lo), "f"(hi)); return r;
}
__device__ __forceinline__ ull fma2(ull a, ull b, ull c) {
    ull d; asm("fma.rn.f32x2 %0, %1, %2, %3;" : "=l"(d) : "l"(a), "l"(b), "l"(c)); return d;
}
__device__ __forceinline__ void unpack2(ull v, float& lo, float& hi) {
    asm("mov.b64 {%0, %1}, %2;" : "=f"(lo), "=f"(hi) : "l"(v));
}

// ---------------- scratch (device globals: no allocation allowed) -----------
__device__ float g_y1[(size_t)BATCH*64*NPTS];   // pre-BN conv1 out
__device__ float g_y2[(size_t)BATCH*128*NPTS];  // pre-BN conv2 out
__device__ float g_y3[(size_t)BATCH*32*NPTS];   // pre-BN conv3 out
__device__ float g_y4[(size_t)BATCH*512*NPTS];  // pre-BN conv4 out
__device__ float g_y5[(size_t)BATCH*256*NPTS];  // pre-BN conv5 out
__device__ float g_y6[(size_t)BATCH*128*NPTS];  // pre-BN conv6 out
__device__ float g_bsum[(size_t)NTILE*512];     // per-tile partial sums
__device__ float g_bsq [(size_t)NTILE*512];     // per-tile partial sumsq
__device__ float g_scale[6][512];               // per-layer BN scale (g*rstd)
__device__ float g_shift[6][512];               // per-layer BN shift (be - m*g*rstd)
__device__ float g_v[BATCH*32];                 // softpool vector
__device__ float g_bias4[BATCH*512];            // folded conv4 bias

// ---------------- GEMM: Y[b,co,n] = sum_ci W[co,ci]*act(X[b,ci,n]) + bias ---
// act = identity (inLayer<0) or BN+ReLU using g_scale/g_shift[inLayer].
// Tile: 64 out-channels x 256 points, K-chunk 16, 256 threads.
// Accumulators are packed f32x2 (2 points per register pair, FFMA2 mainloop).
// If doStats, the epilogue writes per-tile (sum, sumsq) partials per channel.
__global__ void __launch_bounds__(256, 2)
gemm_kernel(const float* __restrict__ W, int wstride,
            const float* __restrict__ bias, int biasPerBatch,
            const float* __restrict__ X, int Ci, int inLayer,
            float* __restrict__ Y, int Co, int outTanh, int doStats)
{
    __shared__ __align__(16) ull   As2[16][65];  // [k][co], value duplicated in both halves
    __shared__ __align__(16) float Xs[16][256];  // [k][n]

    const int t  = threadIdx.x;
    const int tn = t & 15;   // column group 0..15
    const int r  = t >> 4;   // row group    0..15
    const int tilesPerBatch = NPTS / 256;        // 64
    const int b   = blockIdx.y / tilesPerBatch;
    const int n0  = (blockIdx.y % tilesPerBatch) * 256;
    const int co0 = blockIdx.x * 64;

    const float* __restrict__ sc = (inLayer >= 0) ? g_scale[inLayer] : (const float*)0;
    const float* __restrict__ sh = (inLayer >= 0) ? g_shift[inLayer] : (const float*)0;

    ull acc2[4][8];
#pragma unroll
    for (int j = 0; j < 4; j++)
#pragma unroll
        for (int q = 0; q < 8; q++) acc2[j][q] = 0ull;

    for (int k0 = 0; k0 < Ci; k0 += 16) {
        // stage weights (duplicated into both packed halves)
#pragma unroll
        for (int i = 0; i < 4; i++) {
            int lin = i*256 + t;
            int k = lin & 15, co = lin >> 4;
            int ci = k0 + k, cog = co0 + co;
            float w = 0.f;
            if (ci < Ci && cog < Co) w = W[(size_t)cog * wstride + ci];
            As2[k][co] = pack2(w, w);
        }
        // stage inputs: vectorized float4, BN+ReLU applied on the fly
#pragma unroll
        for (int i = 0; i < 4; i++) {
            int fidx = i*256 + t;          // 0..1023 float4 slots
            int k  = fidx >> 6;            // 0..15
            int n4 = fidx & 63;            // 0..63
            int ci = k0 + k;
            float4 v = make_float4(0.f, 0.f, 0.f, 0.f);
            if (ci < Ci) {
                v = *(const float4*)&X[((size_t)b * Ci + ci) * NPTS + n0 + n4*4];
                if (inLayer >= 0) {
                    float a = sc[ci], c = sh[ci];
                    v.x = fmaxf(fmaf(v.x, a, c), 0.f);
                    v.y = fmaxf(fmaf(v.y, a, c), 0.f);
                    v.z = fmaxf(fmaf(v.z, a, c), 0.f);
                    v.w = fmaxf(fmaf(v.w, a, c), 0.f);
                }
            }
            *(float4*)&Xs[k][n4*4] = v;
        }
        __syncthreads();

#pragma unroll
        for (int kk = 0; kk < 16; kk++) {
            ull a0 = As2[kk][r*4 + 0];
            ull a1 = As2[kk][r*4 + 1];
            ull a2 = As2[kk][r*4 + 2];
            ull a3 = As2[kk][r*4 + 3];
#pragma unroll
            for (int g = 0; g < 4; g++) {
                ulonglong2 xv = *(const ulonglong2*)&Xs[kk][g*64 + tn*4];
                acc2[0][g*2+0] = fma2(a0, xv.x, acc2[0][g*2+0]);
                acc2[0][g*2+1] = fma2(a0, xv.y, acc2[0][g*2+1]);
                acc2[1][g*2+0] = fma2(a1, xv.x, acc2[1][g*2+0]);
                acc2[1][g*2+1] = fma2(a1, xv.y, acc2[1][g*2+1]);
                acc2[2][g*2+0] = fma2(a2, xv.x, acc2[2][g*2+0]);
                acc2[2][g*2+1] = fma2(a2, xv.y, acc2[2][g*2+1]);
                acc2[3][g*2+0] = fma2(a3, xv.x, acc2[3][g*2+0]);
                acc2[3][g*2+1] = fma2(a3, xv.y, acc2[3][g*2+1]);
            }
        }
        __syncthreads();
    }

    // epilogue (+ fused BN stats partials)
    const int tile = blockIdx.y;
#pragma unroll
    for (int j = 0; j < 4; j++) {
        int cog = co0 + r*4 + j;
        bool valid = (cog < Co);
        float bs = 0.f;
        if (valid) bs = biasPerBatch ? bias[(size_t)b * Co + cog] : bias[cog];
        float s = 0.f, q = 0.f;
        float* yr = valid ? &Y[((size_t)b * Co + cog) * NPTS + n0] : (float*)0;
#pragma unroll
        for (int g = 0; g < 4; g++) {
            float4 o;
            unpack2(acc2[j][g*2+0], o.x, o.y);
            unpack2(acc2[j][g*2+1], o.z, o.w);
            o.x += bs; o.y += bs; o.z += bs; o.w += bs;
            if (doStats) {
                s += (o.x + o.y) + (o.z + o.w);
                q = fmaf(o.x, o.x, q); q = fmaf(o.y, o.y, q);
                q = fmaf(o.z, o.z, q); q = fmaf(o.w, o.w, q);
            }
            if (outTanh) { o.x = tanhf(o.x); o.y = tanhf(o.y); o.z = tanhf(o.z); o.w = tanhf(o.w); }
            if (valid) *(float4*)&yr[g*64 + tn*4] = o;
        }
        if (doStats) {
            // deterministic width-16 tree reduce (all 32 lanes participate)
#pragma unroll
            for (int off = 8; off; off >>= 1) {
                s += __shfl_down_sync(0xffffffffu, s, off, 16);
                q += __shfl_down_sync(0xffffffffu, q, off, 16);
            }
            if (tn == 0 && valid) {
                g_bsum[(size_t)tile * 512 + cog] = s;
                g_bsq [(size_t)tile * 512 + cog] = q;
            }
        }
    }
}

// ---------------- finalize: reduce tile partials -> BN scale/shift ----------
__global__ void finalize_kernel(const float* __restrict__ gamma,
                                const float* __restrict__ beta, int C, int layer)
{
    int c = blockIdx.x * blockDim.x + threadIdx.x;
    if (c >= C) return;
    float s = 0.f, q = 0.f;
    for (int tI = 0; tI < NTILE; tI++) {
        s += g_bsum[(size_t)tI * 512 + c];
        q += g_bsq [(size_t)tI * 512 + c];
    }
    float m   = s * (1.0f / BNTOT);
    float var = q * (1.0f / BNTOT) - m * m;
    float rstd = rsqrtf(var + 1e-5f);
    float scl  = gamma[c] * rstd;
    g_scale[layer][c] = scl;
    g_shift[layer][c] = fmaf(-m, scl, beta[c]);
}

// ---------------- SoftPool: 16 smallest (stable ties) per (b, key channel) --
__global__ void __launch_bounds__(256)
softpool_kernel(const float* __restrict__ w9, const float* __restrict__ b9)
{
    const int b = blockIdx.x >> 5;
    const int k = blockIdx.x & 31;
    const int t = threadIdx.x;

    __shared__ float sVal[256];
    __shared__ int   sIdx[256];
    __shared__ int   selIdx[16];

    const float sc = g_scale[2][k], sh = g_shift[2][k];
    const float* __restrict__ row = &g_y3[((size_t)b * 32 + k) * NPTS];

    float lastV = -3.402823466e38f;
    int   lastI = -1;

    for (int p = 0; p < 16; p++) {
        float bv = 3.402823466e38f;
        int   bi = NPTS;
        for (int n = t; n < NPTS; n += 256) {
            float val = fmaf(row[n], sc, sh);
            bool elig = (val > lastV) || (val == lastV && n > lastI);
            if (elig && (val < bv || (val == bv && n < bi))) { bv = val; bi = n; }
        }
        sVal[t] = bv; sIdx[t] = bi;
        __syncthreads();
        for (int st = 128; st > 0; st >>= 1) {
            if (t < st) {
                float ov = sVal[t + st]; int oi = sIdx[t + st];
                if (ov < sVal[t] || (ov == sVal[t] && oi < sIdx[t])) { sVal[t] = ov; sIdx[t] = oi; }
            }
            __syncthreads();
        }
        lastV = sVal[0]; lastI = sIdx[0];
        if (t == 0) selIdx[p] = sIdx[0];
        __syncthreads();
    }

    // v[b,k]
    float part = 0.f;
    for (int i = t; i < 512; i += 256) {   // 32 channels x 16 positions
        int c = i >> 4, p = i & 15;
        int n = selIdx[p];
        float val = fmaf(g_y3[((size_t)b * 32 + c) * NPTS + n], g_scale[2][c], g_shift[2][c]);
        part = fmaf(w9[c * 16 + p], val, part);
    }
    sVal[t] = part;
    __syncthreads();
    for (int st = 128; st > 0; st >>= 1) {
        if (t < st) sVal[t] += sVal[t + st];
        __syncthreads();
    }
    if (t == 0) g_v[b * 32 + k] = sVal[0] + b9[0];
}

// ---------------- fold glob into conv4 bias ---------------------------------
__global__ void bias4_kernel(const float* __restrict__ w4, const float* __restrict__ b4)
{
    int idx = blockIdx.x * 256 + threadIdx.x;   // 16*512
    if (idx >= BATCH * 512) return;
    int b = idx >> 9, co = idx & 511;
    float s = b4[co];
#pragma unroll
    for (int k = 0; k < 32; k++) s = fmaf(w4[co * 96 + k], g_v[b * 32 + k], s);
    g_bias4[idx] = s;
}

// ---------------------------------------------------------------------------
extern "C" void kernel_launch(void* const* d_in, const int* in_sizes, int n_in,
                              void* d_out, int out_size)
{
    const float* x   = (const float*)d_in[0];
    const float* w1  = (const float*)d_in[1];  const float* b1  = (const float*)d_in[2];
    const float* g1  = (const float*)d_in[3];  const float* be1 = (const float*)d_in[4];
    const float* w2  = (const float*)d_in[5];  const float* b2  = (const float*)d_in[6];
    const float* g2  = (const float*)d_in[7];  const float* be2 = (const float*)d_in[8];
    const float* w3  = (const float*)d_in[9];  const float* b3  = (const float*)d_in[10];
    const float* g3  = (const float*)d_in[11]; const float* be3 = (const float*)d_in[12];
    const float* w9  = (const float*)d_in[13]; const float* b9  = (const float*)d_in[14];
    const float* w4  = (const float*)d_in[15]; const float* b4  = (const float*)d_in[16];
    const float* g4  = (const float*)d_in[17]; const float* be4 = (const float*)d_in[18];
    const float* w5  = (const float*)d_in[19]; const float* b5  = (const float*)d_in[20];
    const float* g5  = (const float*)d_in[21]; const float* be5 = (const float*)d_in[22];
    const float* w6  = (const float*)d_in[23]; const float* b6  = (const float*)d_in[24];
    const float* g6  = (const float*)d_in[25]; const float* be6 = (const float*)d_in[26];
    const float* w7  = (const float*)d_in[27]; const float* b7  = (const float*)d_in[28];

    float *y1, *y2, *y3, *y4, *y5, *y6, *bias4p;
    cudaGetSymbolAddress((void**)&y1, g_y1);
    cudaGetSymbolAddress((void**)&y2, g_y2);
    cudaGetSymbolAddress((void**)&y3, g_y3);
    cudaGetSymbolAddress((void**)&y4, g_y4);
    cudaGetSymbolAddress((void**)&y5, g_y5);
    cudaGetSymbolAddress((void**)&y6, g_y6);
    cudaGetSymbolAddress((void**)&bias4p, g_bias4);

    const dim3 blk(256);

    // L1: 4 -> 64 (raw input)
    gemm_kernel<<<dim3(1, NTILE), blk>>>(w1, 4, b1, 0, x, 4, -1, y1, 64, 0, 1);
    finalize_kernel<<<1, 256>>>(g1, be1, 64, 0);

    // L2: 64 -> 128
    gemm_kernel<<<dim3(2, NTILE), blk>>>(w2, 64, b2, 0, y1, 64, 0, y2, 128, 0, 1);
    finalize_kernel<<<1, 256>>>(g2, be2, 128, 1);

    // L3: 128 -> 32 (BN only, consumed by softpool)
    gemm_kernel<<<dim3(1, NTILE), blk>>>(w3, 128, b3, 0, y2, 128, 1, y3, 32, 0, 1);
    finalize_kernel<<<1, 256>>>(g3, be3, 32, 2);

    // SoftPool + fold glob into conv4 bias
    softpool_kernel<<<512, 256>>>(w9, b9);
    bias4_kernel<<<32, 256>>>(w4, b4);

    // L4: effectively 64 -> 512 on h1, per-batch bias (glob folded)
    gemm_kernel<<<dim3(8, NTILE), blk>>>(w4 + 32, 96, bias4p, 1, y1, 64, 0, y4, 512, 0, 1);
    finalize_kernel<<<2, 256>>>(g4, be4, 512, 3);

    // L5: 512 -> 256
    gemm_kernel<<<dim3(4, NTILE), blk>>>(w5, 512, b5, 0, y4, 512, 3, y5, 256, 0, 1);
    finalize_kernel<<<1, 256>>>(g5, be5, 256, 4);

    // L6: 256 -> 128
    gemm_kernel<<<dim3(2, NTILE), blk>>>(w6, 256, b6, 0, y5, 256, 4, y6, 128, 0, 1);
    finalize_kernel<<<1, 256>>>(g6, be6, 128, 5);

    // L7: 128 -> 3, tanh, straight to output
    gemm_kernel<<<dim3(1, NTILE), blk>>>(w7, 128, b7, 0, y6, 128, 5, (float*)d_out, 3, 1, 0);
}

// round 3
// speedup vs baseline: 1.3554x; 1.3554x over previous
#include <cuda_runtime.h>
#include <math.h>

#define BATCH 16
#define NPTS  16384
#define BNTOT (BATCH*NPTS)
#define NTILE (BNTOT/256)   // 1024 column tiles

typedef unsigned long long ull;

// ---------------- packed f32x2 helpers --------------------------------------
__device__ __forceinline__ ull pack2(float lo, float hi) {
    ull r; asm("mov.b64 %0, {%1, %2};" : "=l"(r) : "f"(lo), "f"(hi)); return r;
}
__device__ __forceinline__ ull fma2(ull a, ull b, ull c) {
    ull d; asm("fma.rn.f32x2 %0, %1, %2, %3;" : "=l"(d) : "l"(a), "l"(b), "l"(c)); return d;
}
__device__ __forceinline__ void unpack2(ull v, float& lo, float& hi) {
    asm("mov.b64 {%0, %1}, %2;" : "=f"(lo), "=f"(hi) : "l"(v));
}

// ---------------- scratch (device globals: no allocation allowed) -----------
__device__ float g_y1[(size_t)BATCH*64*NPTS];   // pre-BN conv1 out
__device__ float g_y2[(size_t)BATCH*128*NPTS];  // pre-BN conv2 out
__device__ float g_y3[(size_t)BATCH*32*NPTS];   // pre-BN conv3 out
__device__ float g_y4[(size_t)BATCH*512*NPTS];  // pre-BN conv4 out
__device__ float g_y5[(size_t)BATCH*256*NPTS];  // pre-BN conv5 out
__device__ float g_y6[(size_t)BATCH*128*NPTS];  // pre-BN conv6 out
__device__ float g_bsum[(size_t)512*NTILE];     // per-tile partial sums [c][tile]
__device__ float g_bsq [(size_t)512*NTILE];     // per-tile partial sumsq [c][tile]
__device__ float g_scale[6][512];               // per-layer BN scale (g*rstd)
__device__ float g_shift[6][512];               // per-layer BN shift (be - m*g*rstd)
__device__ float g_v[BATCH*32];                 // softpool vector
__device__ float g_bias4[BATCH*512];            // folded conv4 bias

// ---------------- GEMM: Y[b,co,n] = sum_ci W[co,ci]*act(X[b,ci,n]) + bias ---
// act = identity (inLayer<0) or BN+ReLU using g_scale/g_shift[inLayer].
// Tile: 64 out-channels x 256 points, K-chunk 16, 256 threads.
// Register-prefetch pipeline: next chunk's LDGs issue before the compute loop.
// Accumulators are packed f32x2 (FFMA2 mainloop).
__global__ void __launch_bounds__(256, 2)
gemm_kernel(const float* __restrict__ W, int wstride,
            const float* __restrict__ bias, int biasPerBatch,
            const float* __restrict__ X, int Ci, int inLayer,
            float* __restrict__ Y, int Co, int outTanh, int doStats)
{
    __shared__ __align__(16) ull   As2[16][65];  // [k][co], value duplicated in both halves
    __shared__ __align__(16) float Xs[16][256];  // [k][n]

    const int t  = threadIdx.x;
    const int tn = t & 15;   // column group 0..15
    const int r  = t >> 4;   // row group    0..15
    const int tilesPerBatch = NPTS / 256;        // 64
    const int b   = blockIdx.y / tilesPerBatch;
    const int n0  = (blockIdx.y % tilesPerBatch) * 256;
    const int co0 = blockIdx.x * 64;

    const float* __restrict__ sc = (inLayer >= 0) ? g_scale[inLayer] : (const float*)0;
    const float* __restrict__ sh = (inLayer >= 0) ? g_shift[inLayer] : (const float*)0;

    // per-thread staging coordinates (constant across chunks)
    // W: 4 values, lin = i*256 + t -> k = lin&15, co = lin>>4
    // X: 4 float4,  fidx = i*256 + t -> k = fidx>>6, n4 = fidx&63
    ull acc2[4][8];
#pragma unroll
    for (int j = 0; j < 4; j++)
#pragma unroll
        for (int q = 0; q < 8; q++) acc2[j][q] = 0ull;

    const int nChunks = (Ci + 15) >> 4;

    float  wreg[4];
    float4 xreg[4];

    // ---- prologue: load chunk 0 into registers ----
    {
        const int k0 = 0;
#pragma unroll
        for (int i = 0; i < 4; i++) {
            int lin = i*256 + t;
            int k = lin & 15, co = lin >> 4;
            int ci = k0 + k, cog = co0 + co;
            wreg[i] = (ci < Ci && cog < Co) ? W[(size_t)cog * wstride + ci] : 0.f;
        }
#pragma unroll
        for (int i = 0; i < 4; i++) {
            int fidx = i*256 + t;
            int k  = fidx >> 6;
            int n4 = fidx & 63;
            int ci = k0 + k;
            xreg[i] = (ci < Ci) ? *(const float4*)&X[((size_t)b * Ci + ci) * NPTS + n0 + n4*4]
                                : make_float4(0.f,0.f,0.f,0.f);
        }
    }

    for (int c = 0; c < nChunks; c++) {
        const int k0 = c << 4;
        if (c > 0) __syncthreads();          // previous compute done -> smem free

        // ---- STS: regs -> smem (BN+ReLU applied here) ----
#pragma unroll
        for (int i = 0; i < 4; i++) {
            int lin = i*256 + t;
            int k = lin & 15, co = lin >> 4;
            float w = wreg[i];
            As2[k][co] = pack2(w, w);
        }
#pragma unroll
        for (int i = 0; i < 4; i++) {
            int fidx = i*256 + t;
            int k  = fidx >> 6;
            int n4 = fidx & 63;
            int ci = k0 + k;
            float4 v = xreg[i];
            if (inLayer >= 0 && ci < Ci) {
                float a = sc[ci], cc = sh[ci];
                v.x = fmaxf(fmaf(v.x, a, cc), 0.f);
                v.y = fmaxf(fmaf(v.y, a, cc), 0.f);
                v.z = fmaxf(fmaf(v.z, a, cc), 0.f);
                v.w = fmaxf(fmaf(v.w, a, cc), 0.f);
            }
            *(float4*)&Xs[k][n4*4] = v;
        }
        __syncthreads();

        // ---- prefetch next chunk (LDGs in flight during compute) ----
        if (c + 1 < nChunks) {
            const int k0n = k0 + 16;
#pragma unroll
            for (int i = 0; i < 4; i++) {
                int lin = i*256 + t;
                int k = lin & 15, co = lin >> 4;
                int ci = k0n + k, cog = co0 + co;
                wreg[i] = (ci < Ci && cog < Co) ? W[(size_t)cog * wstride + ci] : 0.f;
            }
#pragma unroll
            for (int i = 0; i < 4; i++) {
                int fidx = i*256 + t;
                int k  = fidx >> 6;
                int n4 = fidx & 63;
                int ci = k0n + k;
                xreg[i] = (ci < Ci) ? *(const float4*)&X[((size_t)b * Ci + ci) * NPTS + n0 + n4*4]
                                    : make_float4(0.f,0.f,0.f,0.f);
            }
        }

        // ---- compute 16 k-steps ----
#pragma unroll
        for (int kk = 0; kk < 16; kk++) {
            ull a0 = As2[kk][r*4 + 0];
            ull a1 = As2[kk][r*4 + 1];
            ull a2 = As2[kk][r*4 + 2];
            ull a3 = As2[kk][r*4 + 3];
#pragma unroll
            for (int g = 0; g < 4; g++) {
                ulonglong2 xv = *(const ulonglong2*)&Xs[kk][g*64 + tn*4];
                acc2[0][g*2+0] = fma2(a0, xv.x, acc2[0][g*2+0]);
                acc2[0][g*2+1] = fma2(a0, xv.y, acc2[0][g*2+1]);
                acc2[1][g*2+0] = fma2(a1, xv.x, acc2[1][g*2+0]);
                acc2[1][g*2+1] = fma2(a1, xv.y, acc2[1][g*2+1]);
                acc2[2][g*2+0] = fma2(a2, xv.x, acc2[2][g*2+0]);
                acc2[2][g*2+1] = fma2(a2, xv.y, acc2[2][g*2+1]);
                acc2[3][g*2+0] = fma2(a3, xv.x, acc2[3][g*2+0]);
                acc2[3][g*2+1] = fma2(a3, xv.y, acc2[3][g*2+1]);
            }
        }
    }

    // epilogue (+ fused BN stats partials, layout [c][tile] for fast finalize)
    const int tile = blockIdx.y;
#pragma unroll
    for (int j = 0; j < 4; j++) {
        int cog = co0 + r*4 + j;
        bool valid = (cog < Co);
        float bs = 0.f;
        if (valid) bs = biasPerBatch ? bias[(size_t)b * Co + cog] : bias[cog];
        float s = 0.f, q = 0.f;
        float* yr = valid ? &Y[((size_t)b * Co + cog) * NPTS + n0] : (float*)0;
#pragma unroll
        for (int g = 0; g < 4; g++) {
            float4 o;
            unpack2(acc2[j][g*2+0], o.x, o.y);
            unpack2(acc2[j][g*2+1], o.z, o.w);
            o.x += bs; o.y += bs; o.z += bs; o.w += bs;
            if (doStats) {
                s += (o.x + o.y) + (o.z + o.w);
                q = fmaf(o.x, o.x, q); q = fmaf(o.y, o.y, q);
                q = fmaf(o.z, o.z, q); q = fmaf(o.w, o.w, q);
            }
            if (outTanh) { o.x = tanhf(o.x); o.y = tanhf(o.y); o.z = tanhf(o.z); o.w = tanhf(o.w); }
            if (valid) *(float4*)&yr[g*64 + tn*4] = o;
        }
        if (doStats) {
            // deterministic width-16 tree reduce
#pragma unroll
            for (int off = 8; off; off >>= 1) {
                s += __shfl_down_sync(0xffffffffu, s, off, 16);
                q += __shfl_down_sync(0xffffffffu, q, off, 16);
            }
            if (tn == 0 && valid) {
                g_bsum[(size_t)cog * NTILE + tile] = s;
                g_bsq [(size_t)cog * NTILE + tile] = q;
            }
        }
    }
}

// ---------------- finalize: one block per channel, parallel tree ------------
__global__ void __launch_bounds__(256)
finalize_kernel(const float* __restrict__ gamma,
                const float* __restrict__ beta, int layer)
{
    const int c = blockIdx.x;
    const int t = threadIdx.x;
    float s = 0.f, q = 0.f;
#pragma unroll
    for (int i = 0; i < NTILE/256; i++) {
        s += g_bsum[(size_t)c * NTILE + i*256 + t];
        q += g_bsq [(size_t)c * NTILE + i*256 + t];
    }
    __shared__ float ss[256], sq[256];
    ss[t] = s; sq[t] = q;
    __syncthreads();
    for (int st = 128; st > 0; st >>= 1) {
        if (t < st) { ss[t] += ss[t + st]; sq[t] += sq[t + st]; }
        __syncthreads();
    }
    if (t == 0) {
        float m   = ss[0] * (1.0f / BNTOT);
        float var = sq[0] * (1.0f / BNTOT) - m * m;
        float rstd = rsqrtf(var + 1e-5f);
        float scl  = gamma[c] * rstd;
        g_scale[layer][c] = scl;
        g_shift[layer][c] = fmaf(-m, scl, beta[c]);
    }
}

// ---------------- SoftPool: 16 smallest (stable ties) per (b, key channel) --
__global__ void __launch_bounds__(256)
softpool_kernel(const float* __restrict__ w9, const float* __restrict__ b9)
{
    const int b = blockIdx.x >> 5;
    const int k = blockIdx.x & 31;
    const int t = threadIdx.x;

    __shared__ float sVal[256];
    __shared__ int   sIdx[256];
    __shared__ int   selIdx[16];

    const float sc = g_scale[2][k], sh = g_shift[2][k];
    const float* __restrict__ row = &g_y3[((size_t)b * 32 + k) * NPTS];

    float lastV = -3.402823466e38f;
    int   lastI = -1;

    for (int p = 0; p < 16; p++) {
        float bv = 3.402823466e38f;
        int   bi = NPTS;
        for (int n = t; n < NPTS; n += 256) {
            float val = fmaf(row[n], sc, sh);
            bool elig = (val > lastV) || (val == lastV && n > lastI);
            if (elig && (val < bv || (val == bv && n < bi))) { bv = val; bi = n; }
        }
        sVal[t] = bv; sIdx[t] = bi;
        __syncthreads();
        for (int st = 128; st > 0; st >>= 1) {
            if (t < st) {
                float ov = sVal[t + st]; int oi = sIdx[t + st];
                if (ov < sVal[t] || (ov == sVal[t] && oi < sIdx[t])) { sVal[t] = ov; sIdx[t] = oi; }
            }
            __syncthreads();
        }
        lastV = sVal[0]; lastI = sIdx[0];
        if (t == 0) selIdx[p] = sIdx[0];
        __syncthreads();
    }

    // v[b,k]
    float part = 0.f;
    for (int i = t; i < 512; i += 256) {   // 32 channels x 16 positions
        int c = i >> 4, p = i & 15;
        int n = selIdx[p];
        float val = fmaf(g_y3[((size_t)b * 32 + c) * NPTS + n], g_scale[2][c], g_shift[2][c]);
        part = fmaf(w9[c * 16 + p], val, part);
    }
    sVal[t] = part;
    __syncthreads();
    for (int st = 128; st > 0; st >>= 1) {
        if (t < st) sVal[t] += sVal[t + st];
        __syncthreads();
    }
    if (t == 0) g_v[b * 32 + k] = sVal[0] + b9[0];
}

// ---------------- fold glob into conv4 bias ---------------------------------
__global__ void bias4_kernel(const float* __restrict__ w4, const float* __restrict__ b4)
{
    int idx = blockIdx.x * 256 + threadIdx.x;   // 16*512
    if (idx >= BATCH * 512) return;
    int b = idx >> 9, co = idx & 511;
    float s = b4[co];
#pragma unroll
    for (int k = 0; k < 32; k++) s = fmaf(w4[co * 96 + k], g_v[b * 32 + k], s);
    g_bias4[idx] = s;
}

// ---------------------------------------------------------------------------
extern "C" void kernel_launch(void* const* d_in, const int* in_sizes, int n_in,
                              void* d_out, int out_size)
{
    const float* x   = (const float*)d_in[0];
    const float* w1  = (const float*)d_in[1];  const float* b1  = (const float*)d_in[2];
    const float* g1  = (const float*)d_in[3];  const float* be1 = (const float*)d_in[4];
    const float* w2  = (const float*)d_in[5];  const float* b2  = (const float*)d_in[6];
    const float* g2  = (const float*)d_in[7];  const float* be2 = (const float*)d_in[8];
    const float* w3  = (const float*)d_in[9];  const float* b3  = (const float*)d_in[10];
    const float* g3  = (const float*)d_in[11]; const float* be3 = (const float*)d_in[12];
    const float* w9  = (const float*)d_in[13]; const float* b9  = (const float*)d_in[14];
    const float* w4  = (const float*)d_in[15]; const float* b4  = (const float*)d_in[16];
    const float* g4  = (const float*)d_in[17]; const float* be4 = (const float*)d_in[18];
    const float* w5  = (const float*)d_in[19]; const float* b5  = (const float*)d_in[20];
    const float* g5  = (const float*)d_in[21]; const float* be5 = (const float*)d_in[22];
    const float* w6  = (const float*)d_in[23]; const float* b6  = (const float*)d_in[24];
    const float* g6  = (const float*)d_in[25]; const float* be6 = (const float*)d_in[26];
    const float* w7  = (const float*)d_in[27]; const float* b7  = (const float*)d_in[28];

    float *y1, *y2, *y3, *y4, *y5, *y6, *bias4p;
    cudaGetSymbolAddress((void**)&y1, g_y1);
    cudaGetSymbolAddress((void**)&y2, g_y2);
    cudaGetSymbolAddress((void**)&y3, g_y3);
    cudaGetSymbolAddress((void**)&y4, g_y4);
    cudaGetSymbolAddress((void**)&y5, g_y5);
    cudaGetSymbolAddress((void**)&y6, g_y6);
    cudaGetSymbolAddress((void**)&bias4p, g_bias4);

    const dim3 blk(256);

    // L1: 4 -> 64 (raw input)
    gemm_kernel<<<dim3(1, NTILE), blk>>>(w1, 4, b1, 0, x, 4, -1, y1, 64, 0, 1);
    finalize_kernel<<<64, 256>>>(g1, be1, 0);

    // L2: 64 -> 128
    gemm_kernel<<<dim3(2, NTILE), blk>>>(w2, 64, b2, 0, y1, 64, 0, y2, 128, 0, 1);
    finalize_kernel<<<128, 256>>>(g2, be2, 1);

    // L3: 128 -> 32 (BN only, consumed by softpool)
    gemm_kernel<<<dim3(1, NTILE), blk>>>(w3, 128, b3, 0, y2, 128, 1, y3, 32, 0, 1);
    finalize_kernel<<<32, 256>>>(g3, be3, 2);

    // SoftPool + fold glob into conv4 bias
    softpool_kernel<<<512, 256>>>(w9, b9);
    bias4_kernel<<<32, 256>>>(w4, b4);

    // L4: effectively 64 -> 512 on h1, per-batch bias (glob folded)
    gemm_kernel<<<dim3(8, NTILE), blk>>>(w4 + 32, 96, bias4p, 1, y1, 64, 0, y4, 512, 0, 1);
    finalize_kernel<<<512, 256>>>(g4, be4, 3);

    // L5: 512 -> 256
    gemm_kernel<<<dim3(4, NTILE), blk>>>(w5, 512, b5, 0, y4, 512, 3, y5, 256, 0, 1);
    finalize_kernel<<<256, 256>>>(g5, be5, 4);

    // L6: 256 -> 128
    gemm_kernel<<<dim3(2, NTILE), blk>>>(w6, 256, b6, 0, y5, 256, 4, y6, 128, 0, 1);
    finalize_kernel<<<128, 256>>>(g6, be6, 5);

    // L7: 128 -> 3, tanh, straight to output
    gemm_kernel<<<dim3(1, NTILE), blk>>>(w7, 128, b7, 0, y6, 128, 5, (float*)d_out, 3, 1, 0);
}

// round 6
// speedup vs baseline: 2.0304x; 1.4980x over previous
#include <cuda_runtime.h>
#include <cuda_fp16.h>
#include <math.h>
#include <stdint.h>

#define BATCH 16
#define NPTS  16384
#define BNTOT (BATCH*NPTS)
#define NTILE (BNTOT/256)   // 1024 column tiles (fp32 gemm path)
#define GST2  16            // stats2 partials (= BATCH)

typedef unsigned long long ull;

// ---------------- packed f32x2 / fp16 helpers --------------------------------
__device__ __forceinline__ ull pack2(float lo, float hi) {
    ull r; asm("mov.b64 %0, {%1, %2};" : "=l"(r) : "f"(lo), "f"(hi)); return r;
}
__device__ __forceinline__ ull fma2(ull a, ull b, ull c) {
    ull d; asm("fma.rn.f32x2 %0, %1, %2, %3;" : "=l"(d) : "l"(a), "l"(b), "l"(c)); return d;
}
__device__ __forceinline__ void unpack2(ull v, float& lo, float& hi) {
    asm("mov.b64 {%0, %1}, %2;" : "=f"(lo), "=f"(hi) : "l"(v));
}
// pack two floats to f16x2 (first arg -> low 16 bits)
__device__ __forceinline__ uint32_t cvt_h2(float lo, float hi) {
    uint32_t r;
    asm("cvt.rn.satfinite.f16x2.f32 %0, %1, %2;" : "=r"(r) : "f"(hi), "f"(lo));
    return r;
}
__device__ __forceinline__ float lo_h2(uint32_t h) {
    __half2 hh = *reinterpret_cast<const __half2*>(&h);
    return __low2float(hh);
}
__device__ __forceinline__ float hi_h2(uint32_t h) {
    __half2 hh = *reinterpret_cast<const __half2*>(&h);
    return __high2float(hh);
}
// warp HMMA: D += A(16x16 f16, row) * B(16x8 f16, col), fp32 accumulate
__device__ __forceinline__ void mma_f16(float d[4], const uint32_t a[4], const uint32_t b[2]) {
    asm volatile("mma.sync.aligned.m16n8k16.row.col.f32.f16.f16.f32 "
        "{%0,%1,%2,%3}, {%4,%5,%6,%7}, {%8,%9}, {%0,%1,%2,%3};"
        : "+f"(d[0]), "+f"(d[1]), "+f"(d[2]), "+f"(d[3])
        : "r"(a[0]), "r"(a[1]), "r"(a[2]), "r"(a[3]), "r"(b[0]), "r"(b[1]));
}

// ---------------- scratch (device globals) ----------------------------------
__device__ float g_y1[(size_t)BATCH*64*NPTS];
__device__ float g_y2[(size_t)BATCH*128*NPTS];
__device__ float g_y3[(size_t)BATCH*32*NPTS];
__device__ float g_y4[(size_t)BATCH*512*NPTS];
__device__ float g_y5[(size_t)BATCH*256*NPTS];
__device__ float g_y6[(size_t)BATCH*128*NPTS];
__device__ float g_bsum[(size_t)512*NTILE];     // fp32-gemm fused stats [c][tile]
__device__ float g_bsq [(size_t)512*NTILE];
__device__ float g_psum2[512*GST2];             // stats2 partials [c][g]
__device__ float g_psq2 [512*GST2];
__device__ float g_scale[6][512];
__device__ float g_shift[6][512];
__device__ float g_v[BATCH*32];
__device__ float g_bias4[BATCH*512];

// =================== HMMA fp16 3-term-split GEMM (layers 2-6) ================
// Y[b,co,n] = sum_ci W[co,ci] * relu(bn(X[b,ci,n])) + bias
// Per 32-channel chunk, virtual K'' = 96 laid out as ONE contiguous stream:
//   A'' (weights, [co][k''/2]) = [ wh(16w) | wh copy(16w) | wl(16w) ]
//   B'' (acts,  [k''/2][n])    = [ xh(16r) | xl(16r)      | xh copy(16r) ]
// One plain mma sweep (kk=0..5) then computes wh*xh + wh*xl + wl*xh exactly.
#define A_STR  52               // 48 data words + 4 pad (bank-conflict-free)
#define B_STR  136              // 128 data words + 8 pad
#define B0_W   3328             // A region = 64*52 words
#define SBUF_W 9856             // + B region 48*136 = 6528 -> per-buffer words

__global__ void __launch_bounds__(256, 2)
hmma_gemm_kernel(const float* __restrict__ W, int wstride,
                 const float* __restrict__ bias, int biasPerBatch,
                 const float* __restrict__ X, int Ci, int inLayer,
                 float* __restrict__ Y, int Co)
{
    extern __shared__ uint32_t sm[];
    const int t    = threadIdx.x;
    const int lane = t & 31, wid = t >> 5;
    const int warpM = wid & 1, warpN = wid >> 1;   // 2 x 4 warps, warp tile 32x32
    const int l4 = lane >> 2, q = lane & 3;
    const int b   = blockIdx.y >> 7;
    const int n0  = (blockIdx.y & 127) * 128;
    const int co0 = blockIdx.x * 64;

    const float* __restrict__ scv = g_scale[inLayer];
    const float* __restrict__ shv = g_shift[inLayer];
    const int nChunks = Ci >> 5;

    float acc[2][4][4];
#pragma unroll
    for (int mt = 0; mt < 2; mt++)
#pragma unroll
        for (int nt = 0; nt < 4; nt++)
#pragma unroll
            for (int j = 0; j < 4; j++) acc[mt][nt][j] = 0.f;

    auto stage = [&](int bufW, int ci0) {
        // ---- A: weights 64co x 32ci -> [wh | wh | wl] ----
#pragma unroll
        for (int i = 0; i < 2; i++) {
            int slot = i*256 + t;
            int co = slot >> 3, f4 = slot & 7;
            int cog = co0 + co;
            float4 w = make_float4(0.f, 0.f, 0.f, 0.f);
            if (cog < Co) w = *(const float4*)&W[(size_t)cog*wstride + ci0 + f4*4];
            uint32_t h0 = cvt_h2(w.x, w.y);
            uint32_t h1 = cvt_h2(w.z, w.w);
            float r0 = w.x - lo_h2(h0);
            float r1 = w.y - hi_h2(h0);
            float r2 = w.z - lo_h2(h1);
            float r3 = w.w - hi_h2(h1);
            uint32_t l0 = cvt_h2(r0, r1);
            uint32_t l1 = cvt_h2(r2, r3);
            int wi = bufW + co*A_STR + f4*2;
            *(uint2*)&sm[wi]      = make_uint2(h0, h1);   // block0: wh
            *(uint2*)&sm[wi + 16] = make_uint2(h0, h1);   // block1: wh copy
            *(uint2*)&sm[wi + 32] = make_uint2(l0, l1);   // block2: wl
        }
        // ---- B: activations 32ci x 128pts (BN+ReLU fused) -> [xh | xl | xh] --
#pragma unroll
        for (int i = 0; i < 2; i++) {
            int slot = i*256 + t;
            int kp = slot >> 5, f4 = slot & 31;
            int c0 = ci0 + kp*2;
            const float4 v0 = *(const float4*)&X[((size_t)b*Ci + c0  )*NPTS + n0 + f4*4];
            const float4 v1 = *(const float4*)&X[((size_t)b*Ci + c0+1)*NPTS + n0 + f4*4];
            float s0 = scv[c0],   h0s = shv[c0];
            float s1 = scv[c0+1], h1s = shv[c0+1];
            float x0[4] = {v0.x, v0.y, v0.z, v0.w};
            float x1[4] = {v1.x, v1.y, v1.z, v1.w};
            uint32_t hw[4], lw[4];
#pragma unroll
            for (int j = 0; j < 4; j++) {
                float a0 = fmaxf(fmaf(x0[j], s0, h0s), 0.f);
                float a1 = fmaxf(fmaf(x1[j], s1, h1s), 0.f);
                uint32_t h = cvt_h2(a0, a1);
                float r0 = a0 - lo_h2(h);
                float r1 = a1 - hi_h2(h);
                hw[j] = h;
                lw[j] = cvt_h2(r0, r1);
            }
            int wi = bufW + B0_W + kp*B_STR + f4*4;
            *(uint4*)&sm[wi]             = make_uint4(hw[0], hw[1], hw[2], hw[3]); // xh
            *(uint4*)&sm[wi + 16*B_STR]  = make_uint4(lw[0], lw[1], lw[2], lw[3]); // xl
            *(uint4*)&sm[wi + 32*B_STR]  = make_uint4(hw[0], hw[1], hw[2], hw[3]); // xh copy
        }
    };

    stage(0, 0);   // prologue: chunk 0 -> buffer 0

    for (int c = 0; c < nChunks; c++) {
        __syncthreads();   // staging(c) visible; compute(c-1) done
        if (c + 1 < nChunks) stage(((c+1) & 1) * SBUF_W, (c+1) << 5);

        const int bufW = (c & 1) * SBUF_W;
        const uint32_t* Aw = sm + bufW;
        const uint32_t* Bx = sm + bufW + B0_W;

#pragma unroll
        for (int kk = 0; kk < 6; kk++) {
            uint32_t af[2][4], bf[4][2];
#pragma unroll
            for (int mt = 0; mt < 2; mt++) {
                int base = (warpM*32 + mt*16 + l4) * A_STR + kk*8 + q;
                af[mt][0] = Aw[base];          af[mt][1] = Aw[base + 8*A_STR];
                af[mt][2] = Aw[base + 4];      af[mt][3] = Aw[base + 8*A_STR + 4];
            }
#pragma unroll
            for (int nt = 0; nt < 4; nt++) {
                int base = (kk*8 + q) * B_STR + warpN*32 + nt*8 + l4;
                bf[nt][0] = Bx[base];  bf[nt][1] = Bx[base + 4*B_STR];
            }
#pragma unroll
            for (int mt = 0; mt < 2; mt++)
#pragma unroll
                for (int nt = 0; nt < 4; nt++)
                    mma_f16(acc[mt][nt], af[mt], bf[nt]);
        }
    }

    // ---- epilogue: D[co][pts] -> channel-major Y, contiguous float2 stores --
#pragma unroll
    for (int mt = 0; mt < 2; mt++) {
        int row0 = co0 + warpM*32 + mt*16 + l4;
        int row1 = row0 + 8;
        float bs0 = 0.f, bs1 = 0.f;
        if (row0 < Co) bs0 = biasPerBatch ? bias[(size_t)b*Co + row0] : bias[row0];
        if (row1 < Co) bs1 = biasPerBatch ? bias[(size_t)b*Co + row1] : bias[row1];
#pragma unroll
        for (int nt = 0; nt < 4; nt++) {
            int col = n0 + warpN*32 + nt*8 + q*2;
            if (row0 < Co)
                *(float2*)&Y[((size_t)b*Co + row0)*NPTS + col] =
                    make_float2(acc[mt][nt][0] + bs0, acc[mt][nt][1] + bs0);
            if (row1 < Co)
                *(float2*)&Y[((size_t)b*Co + row1)*NPTS + col] =
                    make_float2(acc[mt][nt][2] + bs1, acc[mt][nt][3] + bs1);
        }
    }
}

// =================== fp32 FFMA2 GEMM (layers 1 and 7) ========================
__global__ void __launch_bounds__(256, 2)
gemm_kernel(const float* __restrict__ W, int wstride,
            const float* __restrict__ bias, int biasPerBatch,
            const float* __restrict__ X, int Ci, int inLayer,
            float* __restrict__ Y, int Co, int outTanh, int doStats)
{
    __shared__ __align__(16) ull   As2[16][65];
    __shared__ __align__(16) float Xs[16][256];

    const int t  = threadIdx.x;
    const int tn = t & 15;
    const int r  = t >> 4;
    const int tilesPerBatch = NPTS / 256;
    const int b   = blockIdx.y / tilesPerBatch;
    const int n0  = (blockIdx.y % tilesPerBatch) * 256;
    const int co0 = blockIdx.x * 64;

    const float* __restrict__ sc = (inLayer >= 0) ? g_scale[inLayer] : (const float*)0;
    const float* __restrict__ sh = (inLayer >= 0) ? g_shift[inLayer] : (const float*)0;

    ull acc2[4][8];
#pragma unroll
    for (int j = 0; j < 4; j++)
#pragma unroll
        for (int qq = 0; qq < 8; qq++) acc2[j][qq] = 0ull;

    const int nChunks = (Ci + 15) >> 4;
    float  wreg[4];
    float4 xreg[4];

    {
#pragma unroll
        for (int i = 0; i < 4; i++) {
            int lin = i*256 + t;
            int k = lin & 15, co = lin >> 4;
            int ci = k, cog = co0 + co;
            wreg[i] = (ci < Ci && cog < Co) ? W[(size_t)cog * wstride + ci] : 0.f;
        }
#pragma unroll
        for (int i = 0; i < 4; i++) {
            int fidx = i*256 + t;
            int k  = fidx >> 6;
            int n4 = fidx & 63;
            xreg[i] = (k < Ci) ? *(const float4*)&X[((size_t)b * Ci + k) * NPTS + n0 + n4*4]
                               : make_float4(0.f,0.f,0.f,0.f);
        }
    }

    for (int c = 0; c < nChunks; c++) {
        const int k0 = c << 4;
        if (c > 0) __syncthreads();
#pragma unroll
        for (int i = 0; i < 4; i++) {
            int lin = i*256 + t;
            int k = lin & 15, co = lin >> 4;
            float w = wreg[i];
            As2[k][co] = pack2(w, w);
        }
#pragma unroll
        for (int i = 0; i < 4; i++) {
            int fidx = i*256 + t;
            int k  = fidx >> 6;
            int n4 = fidx & 63;
            int ci = k0 + k;
            float4 v = xreg[i];
            if (inLayer >= 0 && ci < Ci) {
                float a = sc[ci], cc = sh[ci];
                v.x = fmaxf(fmaf(v.x, a, cc), 0.f);
                v.y = fmaxf(fmaf(v.y, a, cc), 0.f);
                v.z = fmaxf(fmaf(v.z, a, cc), 0.f);
                v.w = fmaxf(fmaf(v.w, a, cc), 0.f);
            }
            *(float4*)&Xs[k][n4*4] = v;
        }
        __syncthreads();

        if (c + 1 < nChunks) {
            const int k0n = k0 + 16;
#pragma unroll
            for (int i = 0; i < 4; i++) {
                int lin = i*256 + t;
                int k = lin & 15, co = lin >> 4;
                int ci = k0n + k, cog = co0 + co;
                wreg[i] = (ci < Ci && cog < Co) ? W[(size_t)cog * wstride + ci] : 0.f;
            }
#pragma unroll
            for (int i = 0; i < 4; i++) {
                int fidx = i*256 + t;
                int k  = fidx >> 6;
                int n4 = fidx & 63;
                int ci = k0n + k;
                xreg[i] = (ci < Ci) ? *(const float4*)&X[((size_t)b * Ci + ci) * NPTS + n0 + n4*4]
                                    : make_float4(0.f,0.f,0.f,0.f);
            }
        }

#pragma unroll
        for (int kk = 0; kk < 16; kk++) {
            ull a0 = As2[kk][r*4 + 0];
            ull a1 = As2[kk][r*4 + 1];
            ull a2 = As2[kk][r*4 + 2];
            ull a3 = As2[kk][r*4 + 3];
#pragma unroll
            for (int g = 0; g < 4; g++) {
                ulonglong2 xv = *(const ulonglong2*)&Xs[kk][g*64 + tn*4];
                acc2[0][g*2+0] = fma2(a0, xv.x, acc2[0][g*2+0]);
                acc2[0][g*2+1] = fma2(a0, xv.y, acc2[0][g*2+1]);
                acc2[1][g*2+0] = fma2(a1, xv.x, acc2[1][g*2+0]);
                acc2[1][g*2+1] = fma2(a1, xv.y, acc2[1][g*2+1]);
                acc2[2][g*2+0] = fma2(a2, xv.x, acc2[2][g*2+0]);
                acc2[2][g*2+1] = fma2(a2, xv.y, acc2[2][g*2+1]);
                acc2[3][g*2+0] = fma2(a3, xv.x, acc2[3][g*2+0]);
                acc2[3][g*2+1] = fma2(a3, xv.y, acc2[3][g*2+1]);
            }
        }
    }

    const int tile = blockIdx.y;
#pragma unroll
    for (int j = 0; j < 4; j++) {
        int cog = co0 + r*4 + j;
        bool valid = (cog < Co);
        float bs = 0.f;
        if (valid) bs = biasPerBatch ? bias[(size_t)b * Co + cog] : bias[cog];
        float s = 0.f, q = 0.f;
        float* yr = valid ? &Y[((size_t)b * Co + cog) * NPTS + n0] : (float*)0;
#pragma unroll
        for (int g = 0; g < 4; g++) {
            float4 o;
            unpack2(acc2[j][g*2+0], o.x, o.y);
            unpack2(acc2[j][g*2+1], o.z, o.w);
            o.x += bs; o.y += bs; o.z += bs; o.w += bs;
            if (doStats) {
                s += (o.x + o.y) + (o.z + o.w);
                q = fmaf(o.x, o.x, q); q = fmaf(o.y, o.y, q);
                q = fmaf(o.z, o.z, q); q = fmaf(o.w, o.w, q);
            }
            if (outTanh) { o.x = tanhf(o.x); o.y = tanhf(o.y); o.z = tanhf(o.z); o.w = tanhf(o.w); }
            if (valid) *(float4*)&yr[g*64 + tn*4] = o;
        }
        if (doStats) {
#pragma unroll
            for (int off = 8; off; off >>= 1) {
                s += __shfl_down_sync(0xffffffffu, s, off, 16);
                q += __shfl_down_sync(0xffffffffu, q, off, 16);
            }
            if (tn == 0 && valid) {
                g_bsum[(size_t)cog * NTILE + tile] = s;
                g_bsq [(size_t)cog * NTILE + tile] = q;
            }
        }
    }
}

// ---------------- finalize for fused-stats path ([c][NTILE]) ----------------
__global__ void __launch_bounds__(256)
finalize_kernel(const float* __restrict__ gamma,
                const float* __restrict__ beta, int layer)
{
    const int c = blockIdx.x;
    const int t = threadIdx.x;
    float s = 0.f, q = 0.f;
#pragma unroll
    for (int i = 0; i < NTILE/256; i++) {
        s += g_bsum[(size_t)c * NTILE + i*256 + t];
        q += g_bsq [(size_t)c * NTILE + i*256 + t];
    }
    __shared__ float ss[256], sq[256];
    ss[t] = s; sq[t] = q;
    __syncthreads();
    for (int st = 128; st > 0; st >>= 1) {
        if (t < st) { ss[t] += ss[t + st]; sq[t] += sq[t + st]; }
        __syncthreads();
    }
    if (t == 0) {
        float m   = ss[0] * (1.0f / BNTOT);
        float var = sq[0] * (1.0f / BNTOT) - m * m;
        float rstd = rsqrtf(var + 1e-5f);
        float scl  = gamma[c] * rstd;
        g_scale[layer][c] = scl;
        g_shift[layer][c] = fmaf(-m, scl, beta[c]);
    }
}

// ---------------- stats pass for HMMA layers (channel-major Y) --------------
__global__ void __launch_bounds__(256)
stats2_kernel(const float* __restrict__ Y, int C)
{
    const int c = blockIdx.x, g = blockIdx.y;   // g = batch
    const float* __restrict__ row = &Y[((size_t)g * C + c) * NPTS];
    float s = 0.f, q = 0.f;
    for (int i = threadIdx.x; i < NPTS; i += 256) {
        float v = row[i];
        s += v;
        q = fmaf(v, v, q);
    }
    __shared__ float ss[256], sq[256];
    ss[threadIdx.x] = s; sq[threadIdx.x] = q;
    __syncthreads();
    for (int st = 128; st > 0; st >>= 1) {
        if (threadIdx.x < st) {
            ss[threadIdx.x] += ss[threadIdx.x + st];
            sq[threadIdx.x] += sq[threadIdx.x + st];
        }
        __syncthreads();
    }
    if (threadIdx.x == 0) {
        g_psum2[c*GST2 + g] = ss[0];
        g_psq2 [c*GST2 + g] = sq[0];
    }
}

__global__ void finalize2_kernel(const float* __restrict__ gamma,
                                 const float* __restrict__ beta, int layer)
{
    const int c = blockIdx.x;
    const int l = threadIdx.x;   // 32 lanes
    float s = (l < GST2) ? g_psum2[c*GST2 + l] : 0.f;
    float q = (l < GST2) ? g_psq2 [c*GST2 + l] : 0.f;
#pragma unroll
    for (int off = 16; off; off >>= 1) {
        s += __shfl_down_sync(0xffffffffu, s, off);
        q += __shfl_down_sync(0xffffffffu, q, off);
    }
    if (l == 0) {
        float m   = s * (1.0f / BNTOT);
        float var = q * (1.0f / BNTOT) - m * m;
        float rstd = rsqrtf(var + 1e-5f);
        float scl  = gamma[c] * rstd;
        g_scale[layer][c] = scl;
        g_shift[layer][c] = fmaf(-m, scl, beta[c]);
    }
}

// ---------------- SoftPool: 16 smallest (stable ties) per (b, key channel) --
__global__ void __launch_bounds__(256)
softpool_kernel(const float* __restrict__ w9, const float* __restrict__ b9)
{
    const int b = blockIdx.x >> 5;
    const int k = blockIdx.x & 31;
    const int t = threadIdx.x;

    __shared__ float sVal[256];
    __shared__ int   sIdx[256];
    __shared__ int   selIdx[16];

    const float sc = g_scale[2][k], sh = g_shift[2][k];
    const float* __restrict__ row = &g_y3[((size_t)b * 32 + k) * NPTS];

    float lastV = -3.402823466e38f;
    int   lastI = -1;

    for (int p = 0; p < 16; p++) {
        float bv = 3.402823466e38f;
        int   bi = NPTS;
        for (int n = t; n < NPTS; n += 256) {
            float val = fmaf(row[n], sc, sh);
            bool elig = (val > lastV) || (val == lastV && n > lastI);
            if (elig && (val < bv || (val == bv && n < bi))) { bv = val; bi = n; }
        }
        sVal[t] = bv; sIdx[t] = bi;
        __syncthreads();
        for (int st = 128; st > 0; st >>= 1) {
            if (t < st) {
                float ov = sVal[t + st]; int oi = sIdx[t + st];
                if (ov < sVal[t] || (ov == sVal[t] && oi < sIdx[t])) { sVal[t] = ov; sIdx[t] = oi; }
            }
            __syncthreads();
        }
        lastV = sVal[0]; lastI = sIdx[0];
        if (t == 0) selIdx[p] = sIdx[0];
        __syncthreads();
    }

    float part = 0.f;
    for (int i = t; i < 512; i += 256) {
        int c = i >> 4, p = i & 15;
        int n = selIdx[p];
        float val = fmaf(g_y3[((size_t)b * 32 + c) * NPTS + n], g_scale[2][c], g_shift[2][c]);
        part = fmaf(w9[c * 16 + p], val, part);
    }
    sVal[t] = part;
    __syncthreads();
    for (int st = 128; st > 0; st >>= 1) {
        if (t < st) sVal[t] += sVal[t + st];
        __syncthreads();
    }
    if (t == 0) g_v[b * 32 + k] = sVal[0] + b9[0];
}

// ---------------- fold glob into conv4 bias ---------------------------------
__global__ void bias4_kernel(const float* __restrict__ w4, const float* __restrict__ b4)
{
    int idx = blockIdx.x * 256 + threadIdx.x;
    if (idx >= BATCH * 512) return;
    int b = idx >> 9, co = idx & 511;
    float s = b4[co];
#pragma unroll
    for (int k = 0; k < 32; k++) s = fmaf(w4[co * 96 + k], g_v[b * 32 + k], s);
    g_bias4[idx] = s;
}

// ---------------------------------------------------------------------------
extern "C" void kernel_launch(void* const* d_in, const int* in_sizes, int n_in,
                              void* d_out, int out_size)
{
    const float* x   = (const float*)d_in[0];
    const float* w1  = (const float*)d_in[1];  const float* b1  = (const float*)d_in[2];
    const float* g1  = (const float*)d_in[3];  const float* be1 = (const float*)d_in[4];
    const float* w2  = (const float*)d_in[5];  const float* b2  = (const float*)d_in[6];
    const float* g2  = (const float*)d_in[7];  const float* be2 = (const float*)d_in[8];
    const float* w3  = (const float*)d_in[9];  const float* b3  = (const float*)d_in[10];
    const float* g3  = (const float*)d_in[11]; const float* be3 = (const float*)d_in[12];
    const float* w9  = (const float*)d_in[13]; const float* b9  = (const float*)d_in[14];
    const float* w4  = (const float*)d_in[15]; const float* b4  = (const float*)d_in[16];
    const float* g4  = (const float*)d_in[17]; const float* be4 = (const float*)d_in[18];
    const float* w5  = (const float*)d_in[19]; const float* b5  = (const float*)d_in[20];
    const float* g5  = (const float*)d_in[21]; const float* be5 = (const float*)d_in[22];
    const float* w6  = (const float*)d_in[23]; const float* b6  = (const float*)d_in[24];
    const float* g6  = (const float*)d_in[25]; const float* be6 = (const float*)d_in[26];
    const float* w7  = (const float*)d_in[27]; const float* b7  = (const float*)d_in[28];

    float *y1, *y2, *y3, *y4, *y5, *y6, *bias4p;
    cudaGetSymbolAddress((void**)&y1, g_y1);
    cudaGetSymbolAddress((void**)&y2, g_y2);
    cudaGetSymbolAddress((void**)&y3, g_y3);
    cudaGetSymbolAddress((void**)&y4, g_y4);
    cudaGetSymbolAddress((void**)&y5, g_y5);
    cudaGetSymbolAddress((void**)&y6, g_y6);
    cudaGetSymbolAddress((void**)&bias4p, g_bias4);

    const int SMEM = 2 * SBUF_W * 4;   // 78848 B
    cudaFuncSetAttribute(hmma_gemm_kernel, cudaFuncAttributeMaxDynamicSharedMemorySize, SMEM);

    const dim3 blk(256);

    // L1: 4 -> 64 (fp32, fused stats)
    gemm_kernel<<<dim3(1, NTILE), blk>>>(w1, 4, b1, 0, x, 4, -1, y1, 64, 0, 1);
    finalize_kernel<<<64, 256>>>(g1, be1, 0);

    // L2: 64 -> 128 (HMMA fp16 split)
    hmma_gemm_kernel<<<dim3(2, 2048), blk, SMEM>>>(w2, 64, b2, 0, y1, 64, 0, y2, 128);
    stats2_kernel<<<dim3(128, GST2), blk>>>(y2, 128);
    finalize2_kernel<<<128, 32>>>(g2, be2, 1);

    // L3: 128 -> 32 (HMMA)
    hmma_gemm_kernel<<<dim3(1, 2048), blk, SMEM>>>(w3, 128, b3, 0, y2, 128, 1, y3, 32);
    stats2_kernel<<<dim3(32, GST2), blk>>>(y3, 32);
    finalize2_kernel<<<32, 32>>>(g3, be3, 2);

    // SoftPool + fold glob into conv4 bias
    softpool_kernel<<<512, 256>>>(w9, b9);
    bias4_kernel<<<32, 256>>>(w4, b4);

    // L4: 64 -> 512 on h1 (HMMA, per-batch bias, glob folded, weight rows offset 32)
    hmma_gemm_kernel<<<dim3(8, 2048), blk, SMEM>>>(w4 + 32, 96, bias4p, 1, y1, 64, 0, y4, 512);
    stats2_kernel<<<dim3(512, GST2), blk>>>(y4, 512);
    finalize2_kernel<<<512, 32>>>(g4, be4, 3);

    // L5: 512 -> 256 (HMMA)
    hmma_gemm_kernel<<<dim3(4, 2048), blk, SMEM>>>(w5, 512, b5, 0, y4, 512, 3, y5, 256);
    stats2_kernel<<<dim3(256, GST2), blk>>>(y5, 256);
    finalize2_kernel<<<256, 32>>>(g5, be5, 4);

    // L6: 256 -> 128 (HMMA)
    hmma_gemm_kernel<<<dim3(2, 2048), blk, SMEM>>>(w6, 256, b6, 0, y5, 256, 4, y6, 128);
    stats2_kernel<<<dim3(128, GST2), blk>>>(y6, 128);
    finalize2_kernel<<<128, 32>>>(g6, be6, 5);

    // L7: 128 -> 3, tanh, fp32, straight to output
    gemm_kernel<<<dim3(1, NTILE), blk>>>(w7, 128, b7, 0, y6, 128, 5, (float*)d_out, 3, 1, 0);
}

// round 7
// speedup vs baseline: 2.2618x; 1.1140x over previous
#include <cuda_runtime.h>
#include <cuda_fp16.h>
#include <math.h>
#include <stdint.h>

#define BATCH 16
#define NPTS  16384
#define BNTOT (BATCH*NPTS)
#define NTILE (BNTOT/256)   // 1024 column tiles (fp32 gemm path)
#define HPT   8192          // hmma stats partials per channel (2048 tiles x 4 warpN)

typedef unsigned long long ull;

// ---------------- packed f32x2 / fp16 helpers --------------------------------
__device__ __forceinline__ ull pack2(float lo, float hi) {
    ull r; asm("mov.b64 %0, {%1, %2};" : "=l"(r) : "f"(lo), "f"(hi)); return r;
}
__device__ __forceinline__ ull fma2(ull a, ull b, ull c) {
    ull d; asm("fma.rn.f32x2 %0, %1, %2, %3;" : "=l"(d) : "l"(a), "l"(b), "l"(c)); return d;
}
__device__ __forceinline__ void unpack2(ull v, float& lo, float& hi) {
    asm("mov.b64 {%0, %1}, %2;" : "=f"(lo), "=f"(hi) : "l"(v));
}
__device__ __forceinline__ uint32_t cvt_h2(float lo, float hi) {
    uint32_t r;
    asm("cvt.rn.satfinite.f16x2.f32 %0, %1, %2;" : "=r"(r) : "f"(hi), "f"(lo));
    return r;
}
__device__ __forceinline__ float lo_h2(uint32_t h) {
    __half2 hh = *reinterpret_cast<const __half2*>(&h);
    return __low2float(hh);
}
__device__ __forceinline__ float hi_h2(uint32_t h) {
    __half2 hh = *reinterpret_cast<const __half2*>(&h);
    return __high2float(hh);
}
__device__ __forceinline__ void mma_f16(float d[4], const uint32_t a[4], const uint32_t b[2]) {
    asm volatile("mma.sync.aligned.m16n8k16.row.col.f32.f16.f16.f32 "
        "{%0,%1,%2,%3}, {%4,%5,%6,%7}, {%8,%9}, {%0,%1,%2,%3};"
        : "+f"(d[0]), "+f"(d[1]), "+f"(d[2]), "+f"(d[3])
        : "r"(a[0]), "r"(a[1]), "r"(a[2]), "r"(a[3]), "r"(b[0]), "r"(b[1]));
}

// ---------------- scratch (device globals) ----------------------------------
__device__ float g_y1[(size_t)BATCH*64*NPTS];
__device__ float g_y2[(size_t)BATCH*128*NPTS];
__device__ float g_y3[(size_t)BATCH*32*NPTS];
__device__ float g_y4[(size_t)BATCH*512*NPTS];
__device__ float g_y5[(size_t)BATCH*256*NPTS];
__device__ float g_y6[(size_t)BATCH*128*NPTS];
__device__ float g_bsum[(size_t)64*NTILE];      // L1 fused stats [c][tile]
__device__ float g_bsq [(size_t)64*NTILE];
__device__ float g_hsum[(size_t)512*HPT];       // hmma fused stats [c][tile*4+warpN]
__device__ float g_hsq [(size_t)512*HPT];
__device__ float g_scale[6][512];
__device__ float g_shift[6][512];
__device__ float g_v[BATCH*32];
__device__ float g_bias4[BATCH*512];

// =================== HMMA fp16 3-term-split GEMM (layers 2-6) ================
// Per 32-channel chunk, virtual K'' = 96 as one contiguous stream:
//   A'' = [wh | wh | wl],  B'' = [xh | xl | xh]  -> wh*xh + wh*xl + wl*xh.
// BN stats (sum, sumsq of y incl. bias) fused into the epilogue.
#define A_STR  52
#define B_STR  136
#define B0_W   3328
#define SBUF_W 9856

__global__ void __launch_bounds__(256, 2)
hmma_gemm_kernel(const float* __restrict__ W, int wstride,
                 const float* __restrict__ bias, int biasPerBatch,
                 const float* __restrict__ X, int Ci, int inLayer,
                 float* __restrict__ Y, int Co)
{
    extern __shared__ uint32_t sm[];
    const int t    = threadIdx.x;
    const int lane = t & 31, wid = t >> 5;
    const int warpM = wid & 1, warpN = wid >> 1;   // 2 x 4 warps, warp tile 32x32
    const int l4 = lane >> 2, q = lane & 3;
    const int b   = blockIdx.y >> 7;
    const int n0  = (blockIdx.y & 127) * 128;
    const int co0 = blockIdx.x * 64;

    const float* __restrict__ scv = g_scale[inLayer];
    const float* __restrict__ shv = g_shift[inLayer];
    const int nChunks = Ci >> 5;

    float acc[2][4][4];
#pragma unroll
    for (int mt = 0; mt < 2; mt++)
#pragma unroll
        for (int nt = 0; nt < 4; nt++)
#pragma unroll
            for (int j = 0; j < 4; j++) acc[mt][nt][j] = 0.f;

    auto stage = [&](int bufW, int ci0) {
#pragma unroll
        for (int i = 0; i < 2; i++) {
            int slot = i*256 + t;
            int co = slot >> 3, f4 = slot & 7;
            int cog = co0 + co;
            float4 w = make_float4(0.f, 0.f, 0.f, 0.f);
            if (cog < Co) w = *(const float4*)&W[(size_t)cog*wstride + ci0 + f4*4];
            uint32_t h0 = cvt_h2(w.x, w.y);
            uint32_t h1 = cvt_h2(w.z, w.w);
            float r0 = w.x - lo_h2(h0);
            float r1 = w.y - hi_h2(h0);
            float r2 = w.z - lo_h2(h1);
            float r3 = w.w - hi_h2(h1);
            uint32_t l0 = cvt_h2(r0, r1);
            uint32_t l1 = cvt_h2(r2, r3);
            int wi = bufW + co*A_STR + f4*2;
            *(uint2*)&sm[wi]      = make_uint2(h0, h1);   // wh
            *(uint2*)&sm[wi + 16] = make_uint2(h0, h1);   // wh copy
            *(uint2*)&sm[wi + 32] = make_uint2(l0, l1);   // wl
        }
#pragma unroll
        for (int i = 0; i < 2; i++) {
            int slot = i*256 + t;
            int kp = slot >> 5, f4 = slot & 31;
            int c0 = ci0 + kp*2;
            const float4 v0 = *(const float4*)&X[((size_t)b*Ci + c0  )*NPTS + n0 + f4*4];
            const float4 v1 = *(const float4*)&X[((size_t)b*Ci + c0+1)*NPTS + n0 + f4*4];
            float s0 = scv[c0],   h0s = shv[c0];
            float s1 = scv[c0+1], h1s = shv[c0+1];
            float x0[4] = {v0.x, v0.y, v0.z, v0.w};
            float x1[4] = {v1.x, v1.y, v1.z, v1.w};
            uint32_t hw[4], lw[4];
#pragma unroll
            for (int j = 0; j < 4; j++) {
                float a0 = fmaxf(fmaf(x0[j], s0, h0s), 0.f);
                float a1 = fmaxf(fmaf(x1[j], s1, h1s), 0.f);
                uint32_t h = cvt_h2(a0, a1);
                float r0 = a0 - lo_h2(h);
                float r1 = a1 - hi_h2(h);
                hw[j] = h;
                lw[j] = cvt_h2(r0, r1);
            }
            int wi = bufW + B0_W + kp*B_STR + f4*4;
            *(uint4*)&sm[wi]             = make_uint4(hw[0], hw[1], hw[2], hw[3]); // xh
            *(uint4*)&sm[wi + 16*B_STR]  = make_uint4(lw[0], lw[1], lw[2], lw[3]); // xl
            *(uint4*)&sm[wi + 32*B_STR]  = make_uint4(hw[0], hw[1], hw[2], hw[3]); // xh copy
        }
    };

    stage(0, 0);

    for (int c = 0; c < nChunks; c++) {
        __syncthreads();
        if (c + 1 < nChunks) stage(((c+1) & 1) * SBUF_W, (c+1) << 5);

        const int bufW = (c & 1) * SBUF_W;
        const uint32_t* Aw = sm + bufW;
        const uint32_t* Bx = sm + bufW + B0_W;

#pragma unroll
        for (int kk = 0; kk < 6; kk++) {
            uint32_t af[2][4], bf[4][2];
#pragma unroll
            for (int mt = 0; mt < 2; mt++) {
                int base = (warpM*32 + mt*16 + l4) * A_STR + kk*8 + q;
                af[mt][0] = Aw[base];          af[mt][1] = Aw[base + 8*A_STR];
                af[mt][2] = Aw[base + 4];      af[mt][3] = Aw[base + 8*A_STR + 4];
            }
#pragma unroll
            for (int nt = 0; nt < 4; nt++) {
                int base = (kk*8 + q) * B_STR + warpN*32 + nt*8 + l4;
                bf[nt][0] = Bx[base];  bf[nt][1] = Bx[base + 4*B_STR];
            }
#pragma unroll
            for (int mt = 0; mt < 2; mt++)
#pragma unroll
                for (int nt = 0; nt < 4; nt++)
                    mma_f16(acc[mt][nt], af[mt], bf[nt]);
        }
    }

    // ---- epilogue: store Y + fused per-row stats partials ----
    const int tileIdx = blockIdx.y * 4 + warpN;
#pragma unroll
    for (int mt = 0; mt < 2; mt++) {
        int row0 = co0 + warpM*32 + mt*16 + l4;
        int row1 = row0 + 8;
        float bs0 = 0.f, bs1 = 0.f;
        if (row0 < Co) bs0 = biasPerBatch ? bias[(size_t)b*Co + row0] : bias[row0];
        if (row1 < Co) bs1 = biasPerBatch ? bias[(size_t)b*Co + row1] : bias[row1];
        float s0 = 0.f, q0 = 0.f, s1 = 0.f, q1 = 0.f;
#pragma unroll
        for (int nt = 0; nt < 4; nt++) {
            int col = n0 + warpN*32 + nt*8 + q*2;
            float o0 = acc[mt][nt][0] + bs0, o1 = acc[mt][nt][1] + bs0;
            float o2 = acc[mt][nt][2] + bs1, o3 = acc[mt][nt][3] + bs1;
            s0 += o0 + o1;  q0 = fmaf(o0, o0, q0); q0 = fmaf(o1, o1, q0);
            s1 += o2 + o3;  q1 = fmaf(o2, o2, q1); q1 = fmaf(o3, o3, q1);
            if (row0 < Co)
                *(float2*)&Y[((size_t)b*Co + row0)*NPTS + col] = make_float2(o0, o1);
            if (row1 < Co)
                *(float2*)&Y[((size_t)b*Co + row1)*NPTS + col] = make_float2(o2, o3);
        }
        // reduce over q lanes (xor within 4-lane row groups)
        s0 += __shfl_xor_sync(0xffffffffu, s0, 1);  s0 += __shfl_xor_sync(0xffffffffu, s0, 2);
        q0 += __shfl_xor_sync(0xffffffffu, q0, 1);  q0 += __shfl_xor_sync(0xffffffffu, q0, 2);
        s1 += __shfl_xor_sync(0xffffffffu, s1, 1);  s1 += __shfl_xor_sync(0xffffffffu, s1, 2);
        q1 += __shfl_xor_sync(0xffffffffu, q1, 1);  q1 += __shfl_xor_sync(0xffffffffu, q1, 2);
        if (q == 0) {
            if (row0 < Co) {
                g_hsum[(size_t)row0*HPT + tileIdx] = s0;
                g_hsq [(size_t)row0*HPT + tileIdx] = q0;
            }
            if (row1 < Co) {
                g_hsum[(size_t)row1*HPT + tileIdx] = s1;
                g_hsq [(size_t)row1*HPT + tileIdx] = q1;
            }
        }
    }
}

// ---------------- finalize3: reduce HPT partials -> BN scale/shift ----------
__global__ void __launch_bounds__(256)
finalize3_kernel(const float* __restrict__ gamma,
                 const float* __restrict__ beta, int layer)
{
    const int c = blockIdx.x;
    const int t = threadIdx.x;
    float s = 0.f, q = 0.f;
#pragma unroll
    for (int i = 0; i < HPT/256; i++) {
        s += g_hsum[(size_t)c * HPT + i*256 + t];
        q += g_hsq [(size_t)c * HPT + i*256 + t];
    }
    __shared__ float ss[256], sq[256];
    ss[t] = s; sq[t] = q;
    __syncthreads();
    for (int st = 128; st > 0; st >>= 1) {
        if (t < st) { ss[t] += ss[t + st]; sq[t] += sq[t + st]; }
        __syncthreads();
    }
    if (t == 0) {
        float m   = ss[0] * (1.0f / BNTOT);
        float var = sq[0] * (1.0f / BNTOT) - m * m;
        float rstd = rsqrtf(var + 1e-5f);
        float scl  = gamma[c] * rstd;
        g_scale[layer][c] = scl;
        g_shift[layer][c] = fmaf(-m, scl, beta[c]);
    }
}

// =================== fp32 FFMA2 GEMM (layer 1 only) ==========================
__global__ void __launch_bounds__(256, 2)
gemm_kernel(const float* __restrict__ W, int wstride,
            const float* __restrict__ bias,
            const float* __restrict__ X, int Ci,
            float* __restrict__ Y, int Co)
{
    __shared__ __align__(16) ull   As2[16][65];
    __shared__ __align__(16) float Xs[16][256];

    const int t  = threadIdx.x;
    const int tn = t & 15;
    const int r  = t >> 4;
    const int tilesPerBatch = NPTS / 256;
    const int b   = blockIdx.y / tilesPerBatch;
    const int n0  = (blockIdx.y % tilesPerBatch) * 256;
    const int co0 = blockIdx.x * 64;

    ull acc2[4][8];
#pragma unroll
    for (int j = 0; j < 4; j++)
#pragma unroll
        for (int qq = 0; qq < 8; qq++) acc2[j][qq] = 0ull;

    const int nChunks = (Ci + 15) >> 4;
    float  wreg[4];
    float4 xreg[4];

    {
#pragma unroll
        for (int i = 0; i < 4; i++) {
            int lin = i*256 + t;
            int k = lin & 15, co = lin >> 4;
            int ci = k, cog = co0 + co;
            wreg[i] = (ci < Ci && cog < Co) ? W[(size_t)cog * wstride + ci] : 0.f;
        }
#pragma unroll
        for (int i = 0; i < 4; i++) {
            int fidx = i*256 + t;
            int k  = fidx >> 6;
            int n4 = fidx & 63;
            xreg[i] = (k < Ci) ? *(const float4*)&X[((size_t)b * Ci + k) * NPTS + n0 + n4*4]
                               : make_float4(0.f,0.f,0.f,0.f);
        }
    }

    for (int c = 0; c < nChunks; c++) {
        const int k0 = c << 4;
        if (c > 0) __syncthreads();
#pragma unroll
        for (int i = 0; i < 4; i++) {
            int lin = i*256 + t;
            int k = lin & 15, co = lin >> 4;
            float w = wreg[i];
            As2[k][co] = pack2(w, w);
        }
#pragma unroll
        for (int i = 0; i < 4; i++) {
            int fidx = i*256 + t;
            int k  = fidx >> 6;
            int n4 = fidx & 63;
            *(float4*)&Xs[k][n4*4] = xreg[i];
        }
        __syncthreads();

        if (c + 1 < nChunks) {
            const int k0n = k0 + 16;
#pragma unroll
            for (int i = 0; i < 4; i++) {
                int lin = i*256 + t;
                int k = lin & 15, co = lin >> 4;
                int ci = k0n + k, cog = co0 + co;
                wreg[i] = (ci < Ci && cog < Co) ? W[(size_t)cog * wstride + ci] : 0.f;
            }
#pragma unroll
            for (int i = 0; i < 4; i++) {
                int fidx = i*256 + t;
                int k  = fidx >> 6;
                int n4 = fidx & 63;
                int ci = k0n + k;
                xreg[i] = (ci < Ci) ? *(const float4*)&X[((size_t)b * Ci + ci) * NPTS + n0 + n4*4]
                                    : make_float4(0.f,0.f,0.f,0.f);
            }
        }

#pragma unroll
        for (int kk = 0; kk < 16; kk++) {
            ull a0 = As2[kk][r*4 + 0];
            ull a1 = As2[kk][r*4 + 1];
            ull a2 = As2[kk][r*4 + 2];
            ull a3 = As2[kk][r*4 + 3];
#pragma unroll
            for (int g = 0; g < 4; g++) {
                ulonglong2 xv = *(const ulonglong2*)&Xs[kk][g*64 + tn*4];
                acc2[0][g*2+0] = fma2(a0, xv.x, acc2[0][g*2+0]);
                acc2[0][g*2+1] = fma2(a0, xv.y, acc2[0][g*2+1]);
                acc2[1][g*2+0] = fma2(a1, xv.x, acc2[1][g*2+0]);
                acc2[1][g*2+1] = fma2(a1, xv.y, acc2[1][g*2+1]);
                acc2[2][g*2+0] = fma2(a2, xv.x, acc2[2][g*2+0]);
                acc2[2][g*2+1] = fma2(a2, xv.y, acc2[2][g*2+1]);
                acc2[3][g*2+0] = fma2(a3, xv.x, acc2[3][g*2+0]);
                acc2[3][g*2+1] = fma2(a3, xv.y, acc2[3][g*2+1]);
            }
        }
    }

    const int tile = blockIdx.y;
#pragma unroll
    for (int j = 0; j < 4; j++) {
        int cog = co0 + r*4 + j;
        bool valid = (cog < Co);
        float bs = valid ? bias[cog] : 0.f;
        float s = 0.f, q = 0.f;
        float* yr = valid ? &Y[((size_t)b * Co + cog) * NPTS + n0] : (float*)0;
#pragma unroll
        for (int g = 0; g < 4; g++) {
            float4 o;
            unpack2(acc2[j][g*2+0], o.x, o.y);
            unpack2(acc2[j][g*2+1], o.z, o.w);
            o.x += bs; o.y += bs; o.z += bs; o.w += bs;
            s += (o.x + o.y) + (o.z + o.w);
            q = fmaf(o.x, o.x, q); q = fmaf(o.y, o.y, q);
            q = fmaf(o.z, o.z, q); q = fmaf(o.w, o.w, q);
            if (valid) *(float4*)&yr[g*64 + tn*4] = o;
        }
#pragma unroll
        for (int off = 8; off; off >>= 1) {
            s += __shfl_down_sync(0xffffffffu, s, off, 16);
            q += __shfl_down_sync(0xffffffffu, q, off, 16);
        }
        if (tn == 0 && valid) {
            g_bsum[(size_t)cog * NTILE + tile] = s;
            g_bsq [(size_t)cog * NTILE + tile] = q;
        }
    }
}

// ---------------- finalize for L1 ([c][NTILE]) -------------------------------
__global__ void __launch_bounds__(256)
finalize_kernel(const float* __restrict__ gamma,
                const float* __restrict__ beta, int layer)
{
    const int c = blockIdx.x;
    const int t = threadIdx.x;
    float s = 0.f, q = 0.f;
#pragma unroll
    for (int i = 0; i < NTILE/256; i++) {
        s += g_bsum[(size_t)c * NTILE + i*256 + t];
        q += g_bsq [(size_t)c * NTILE + i*256 + t];
    }
    __shared__ float ss[256], sq[256];
    ss[t] = s; sq[t] = q;
    __syncthreads();
    for (int st = 128; st > 0; st >>= 1) {
        if (t < st) { ss[t] += ss[t + st]; sq[t] += sq[t + st]; }
        __syncthreads();
    }
    if (t == 0) {
        float m   = ss[0] * (1.0f / BNTOT);
        float var = sq[0] * (1.0f / BNTOT) - m * m;
        float rstd = rsqrtf(var + 1e-5f);
        float scl  = gamma[c] * rstd;
        g_scale[layer][c] = scl;
        g_shift[layer][c] = fmaf(-m, scl, beta[c]);
    }
}

// ---------------- dedicated L7: 128 -> 3, tanh ------------------------------
__global__ void __launch_bounds__(256)
conv7_kernel(const float* __restrict__ w7, const float* __restrict__ b7,
             const float* __restrict__ Y6, float* __restrict__ out)
{
    __shared__ float sw0[128], sw1[128], sw2[128], ssc[128], ssh[128];
    const int t = threadIdx.x;
    if (t < 128) {
        sw0[t] = w7[t]; sw1[t] = w7[128 + t]; sw2[t] = w7[256 + t];
        ssc[t] = g_scale[5][t]; ssh[t] = g_shift[5][t];
    }
    __syncthreads();

    const int idx = blockIdx.x * 256 + t;        // 65536 threads, 4 pts each
    const int b = idx >> 12;
    const int n = (idx & 4095) * 4;

    float4 a0 = make_float4(0.f,0.f,0.f,0.f);
    float4 a1 = a0, a2 = a0;
#pragma unroll 4
    for (int c = 0; c < 128; c++) {
        float4 v = *(const float4*)&Y6[((size_t)b*128 + c)*NPTS + n];
        float s = ssc[c], h = ssh[c];
        v.x = fmaxf(fmaf(v.x, s, h), 0.f);
        v.y = fmaxf(fmaf(v.y, s, h), 0.f);
        v.z = fmaxf(fmaf(v.z, s, h), 0.f);
        v.w = fmaxf(fmaf(v.w, s, h), 0.f);
        float w0 = sw0[c], w1 = sw1[c], w2 = sw2[c];
        a0.x = fmaf(w0, v.x, a0.x); a0.y = fmaf(w0, v.y, a0.y);
        a0.z = fmaf(w0, v.z, a0.z); a0.w = fmaf(w0, v.w, a0.w);
        a1.x = fmaf(w1, v.x, a1.x); a1.y = fmaf(w1, v.y, a1.y);
        a1.z = fmaf(w1, v.z, a1.z); a1.w = fmaf(w1, v.w, a1.w);
        a2.x = fmaf(w2, v.x, a2.x); a2.y = fmaf(w2, v.y, a2.y);
        a2.z = fmaf(w2, v.z, a2.z); a2.w = fmaf(w2, v.w, a2.w);
    }
    float b0 = b7[0], b1 = b7[1], b2 = b7[2];
    float4 o0 = make_float4(tanhf(a0.x+b0), tanhf(a0.y+b0), tanhf(a0.z+b0), tanhf(a0.w+b0));
    float4 o1 = make_float4(tanhf(a1.x+b1), tanhf(a1.y+b1), tanhf(a1.z+b1), tanhf(a1.w+b1));
    float4 o2 = make_float4(tanhf(a2.x+b2), tanhf(a2.y+b2), tanhf(a2.z+b2), tanhf(a2.w+b2));
    *(float4*)&out[((size_t)b*3 + 0)*NPTS + n] = o0;
    *(float4*)&out[((size_t)b*3 + 1)*NPTS + n] = o1;
    *(float4*)&out[((size_t)b*3 + 2)*NPTS + n] = o2;
}

// ---------------- SoftPool with smem row cache -------------------------------
__global__ void __launch_bounds__(256)
softpool_kernel(const float* __restrict__ w9, const float* __restrict__ b9)
{
    extern __shared__ float cache[];   // 16384 floats (64 KB)
    const int b = blockIdx.x >> 5;
    const int k = blockIdx.x & 31;
    const int t = threadIdx.x;

    __shared__ float sVal[256];
    __shared__ int   sIdx[256];
    __shared__ int   selIdx[16];

    const float sc = g_scale[2][k], sh = g_shift[2][k];
    const float* __restrict__ row = &g_y3[((size_t)b * 32 + k) * NPTS];

    for (int n = t; n < NPTS; n += 256) cache[n] = fmaf(row[n], sc, sh);
    __syncthreads();

    float lastV = -3.402823466e38f;
    int   lastI = -1;

    for (int p = 0; p < 16; p++) {
        float bv = 3.402823466e38f;
        int   bi = NPTS;
        for (int n = t; n < NPTS; n += 256) {
            float val = cache[n];
            bool elig = (val > lastV) || (val == lastV && n > lastI);
            if (elig && (val < bv || (val == bv && n < bi))) { bv = val; bi = n; }
        }
        sVal[t] = bv; sIdx[t] = bi;
        __syncthreads();
        for (int st = 128; st > 0; st >>= 1) {
            if (t < st) {
                float ov = sVal[t + st]; int oi = sIdx[t + st];
                if (ov < sVal[t] || (ov == sVal[t] && oi < sIdx[t])) { sVal[t] = ov; sIdx[t] = oi; }
            }
            __syncthreads();
        }
        lastV = sVal[0]; lastI = sIdx[0];
        if (t == 0) selIdx[p] = sIdx[0];
        __syncthreads();
    }

    float part = 0.f;
    for (int i = t; i < 512; i += 256) {
        int c = i >> 4, p = i & 15;
        int n = selIdx[p];
        float val = fmaf(g_y3[((size_t)b * 32 + c) * NPTS + n], g_scale[2][c], g_shift[2][c]);
        part = fmaf(w9[c * 16 + p], val, part);
    }
    sVal[t] = part;
    __syncthreads();
    for (int st = 128; st > 0; st >>= 1) {
        if (t < st) sVal[t] += sVal[t + st];
        __syncthreads();
    }
    if (t == 0) g_v[b * 32 + k] = sVal[0] + b9[0];
}

// ---------------- fold glob into conv4 bias ---------------------------------
__global__ void bias4_kernel(const float* __restrict__ w4, const float* __restrict__ b4)
{
    int idx = blockIdx.x * 256 + threadIdx.x;
    if (idx >= BATCH * 512) return;
    int b = idx >> 9, co = idx & 511;
    float s = b4[co];
#pragma unroll
    for (int k = 0; k < 32; k++) s = fmaf(w4[co * 96 + k], g_v[b * 32 + k], s);
    g_bias4[idx] = s;
}

// ---------------------------------------------------------------------------
extern "C" void kernel_launch(void* const* d_in, const int* in_sizes, int n_in,
                              void* d_out, int out_size)
{
    const float* x   = (const float*)d_in[0];
    const float* w1  = (const float*)d_in[1];  const float* b1  = (const float*)d_in[2];
    const float* g1  = (const float*)d_in[3];  const float* be1 = (const float*)d_in[4];
    const float* w2  = (const float*)d_in[5];  const float* b2  = (const float*)d_in[6];
    const float* g2  = (const float*)d_in[7];  const float* be2 = (const float*)d_in[8];
    const float* w3  = (const float*)d_in[9];  const float* b3  = (const float*)d_in[10];
    const float* g3  = (const float*)d_in[11]; const float* be3 = (const float*)d_in[12];
    const float* w9  = (const float*)d_in[13]; const float* b9  = (const float*)d_in[14];
    const float* w4  = (const float*)d_in[15]; const float* b4  = (const float*)d_in[16];
    const float* g4  = (const float*)d_in[17]; const float* be4 = (const float*)d_in[18];
    const float* w5  = (const float*)d_in[19]; const float* b5  = (const float*)d_in[20];
    const float* g5  = (const float*)d_in[21]; const float* be5 = (const float*)d_in[22];
    const float* w6  = (const float*)d_in[23]; const float* b6  = (const float*)d_in[24];
    const float* g6  = (const float*)d_in[25]; const float* be6 = (const float*)d_in[26];
    const float* w7  = (const float*)d_in[27]; const float* b7  = (const float*)d_in[28];

    float *y1, *y2, *y3, *y4, *y5, *y6, *bias4p;
    cudaGetSymbolAddress((void**)&y1, g_y1);
    cudaGetSymbolAddress((void**)&y2, g_y2);
    cudaGetSymbolAddress((void**)&y3, g_y3);
    cudaGetSymbolAddress((void**)&y4, g_y4);
    cudaGetSymbolAddress((void**)&y5, g_y5);
    cudaGetSymbolAddress((void**)&y6, g_y6);
    cudaGetSymbolAddress((void**)&bias4p, g_bias4);

    const int SMEM = 2 * SBUF_W * 4;   // 78848 B
    cudaFuncSetAttribute(hmma_gemm_kernel, cudaFuncAttributeMaxDynamicSharedMemorySize, SMEM);
    const int SPSM = NPTS * 4;         // 65536 B
    cudaFuncSetAttribute(softpool_kernel, cudaFuncAttributeMaxDynamicSharedMemorySize, SPSM);

    const dim3 blk(256);

    // L1: 4 -> 64 (fp32, fused stats)
    gemm_kernel<<<dim3(1, NTILE), blk>>>(w1, 4, b1, x, 4, y1, 64);
    finalize_kernel<<<64, 256>>>(g1, be1, 0);

    // L2: 64 -> 128 (HMMA, fused stats)
    hmma_gemm_kernel<<<dim3(2, 2048), blk, SMEM>>>(w2, 64, b2, 0, y1, 64, 0, y2, 128);
    finalize3_kernel<<<128, 256>>>(g2, be2, 1);

    // L3: 128 -> 32 (HMMA)
    hmma_gemm_kernel<<<dim3(1, 2048), blk, SMEM>>>(w3, 128, b3, 0, y2, 128, 1, y3, 32);
    finalize3_kernel<<<32, 256>>>(g3, be3, 2);

    // SoftPool + fold glob into conv4 bias
    softpool_kernel<<<512, 256, SPSM>>>(w9, b9);
    bias4_kernel<<<32, 256>>>(w4, b4);

    // L4: 64 -> 512 on h1 (HMMA, per-batch bias, glob folded, weight rows offset 32)
    hmma_gemm_kernel<<<dim3(8, 2048), blk, SMEM>>>(w4 + 32, 96, bias4p, 1, y1, 64, 0, y4, 512);
    finalize3_kernel<<<512, 256>>>(g4, be4, 3);

    // L5: 512 -> 256 (HMMA)
    hmma_gemm_kernel<<<dim3(4, 2048), blk, SMEM>>>(w5, 512, b5, 0, y4, 512, 3, y5, 256);
    finalize3_kernel<<<256, 256>>>(g5, be5, 4);

    // L6: 256 -> 128 (HMMA)
    hmma_gemm_kernel<<<dim3(2, 2048), blk, SMEM>>>(w6, 256, b6, 0, y5, 256, 4, y6, 128);
    finalize3_kernel<<<128, 256>>>(g6, be6, 5);

    // L7: 128 -> 3, tanh, dedicated kernel, straight to output
    conv7_kernel<<<BNTOT/4/256, blk>>>(w7, b7, y6, (float*)d_out);
}

// round 8
// speedup vs baseline: 2.6240x; 1.1602x over previous
#include <cuda_runtime.h>
#include <cuda_fp16.h>
#include <math.h>
#include <stdint.h>

#define BATCH 16
#define NPTS  16384
#define BNTOT (BATCH*NPTS)
#define NTILE (BNTOT/256)   // 1024 column tiles (fp32 gemm path)
#define HPT   8192          // hmma stats partials per channel

typedef unsigned long long ull;

// ---------------- packed f32x2 / fp16 helpers --------------------------------
__device__ __forceinline__ ull pack2(float lo, float hi) {
    ull r; asm("mov.b64 %0, {%1, %2};" : "=l"(r) : "f"(lo), "f"(hi)); return r;
}
__device__ __forceinline__ ull fma2(ull a, ull b, ull c) {
    ull d; asm("fma.rn.f32x2 %0, %1, %2, %3;" : "=l"(d) : "l"(a), "l"(b), "l"(c)); return d;
}
__device__ __forceinline__ void unpack2(ull v, float& lo, float& hi) {
    asm("mov.b64 {%0, %1}, %2;" : "=f"(lo), "=f"(hi) : "l"(v));
}
__device__ __forceinline__ uint32_t cvt_h2(float lo, float hi) {
    uint32_t r;
    asm("cvt.rn.satfinite.f16x2.f32 %0, %1, %2;" : "=r"(r) : "f"(hi), "f"(lo));
    return r;
}
__device__ __forceinline__ float lo_h2(uint32_t h) {
    __half2 hh = *reinterpret_cast<const __half2*>(&h);
    return __low2float(hh);
}
__device__ __forceinline__ float hi_h2(uint32_t h) {
    __half2 hh = *reinterpret_cast<const __half2*>(&h);
    return __high2float(hh);
}
__device__ __forceinline__ void mma_f16(float d[4], const uint32_t a[4], const uint32_t b[2]) {
    asm volatile("mma.sync.aligned.m16n8k16.row.col.f32.f16.f16.f32 "
        "{%0,%1,%2,%3}, {%4,%5,%6,%7}, {%8,%9}, {%0,%1,%2,%3};"
        : "+f"(d[0]), "+f"(d[1]), "+f"(d[2]), "+f"(d[3])
        : "r"(a[0]), "r"(a[1]), "r"(a[2]), "r"(a[3]), "r"(b[0]), "r"(b[1]));
}

// ---------------- scratch (device globals) ----------------------------------
__device__ float g_y1[(size_t)BATCH*64*NPTS];
__device__ float g_y2[(size_t)BATCH*128*NPTS];
__device__ float g_y3[(size_t)BATCH*32*NPTS];
__device__ float g_y4[(size_t)BATCH*512*NPTS];
__device__ float g_y5[(size_t)BATCH*256*NPTS];
__device__ float g_y6[(size_t)BATCH*128*NPTS];
__device__ float g_bsum[(size_t)64*NTILE];      // L1 fused stats [c][tile]
__device__ float g_bsq [(size_t)64*NTILE];
__device__ float g_hsum[(size_t)512*HPT];       // hmma fused stats [c][tile*4+warpN]
__device__ float g_hsq [(size_t)512*HPT];
__device__ float g_scale[6][512];
__device__ float g_shift[6][512];
__device__ float g_v[BATCH*32];
__device__ float g_bias4[BATCH*512];

// =================== HMMA fp16 3-term-split GEMM (layers 2-6) ================
// Per 32-channel chunk: A = [wh(16w) | wl(16w)], B = [xh(16r) | xl(16r)].
// Per-kk offset tables sweep wh*xh, wh*xl, wl*xh (6 k16 steps, fp32 accum).
// Software pipeline: LDG(c+1)->regs issued before compute(c); cvt+STS at loop top.
#define A_STR  36               // 32 data words + 4 pad
#define B_STR  136              // 128 data words + 8 pad
#define B0_W   2304             // A region = 64*36 words
#define SBUF_W 6656             // + B region 32*136 = 4352 words (26.6 KB/buf)

__global__ void __launch_bounds__(256, 2)
hmma_gemm_kernel(const float* __restrict__ W, int wstride,
                 const float* __restrict__ bias, int biasPerBatch,
                 const float* __restrict__ X, int Ci, int inLayer,
                 float* __restrict__ Y, int Co)
{
    extern __shared__ uint32_t sm[];
    const int t    = threadIdx.x;
    const int lane = t & 31, wid = t >> 5;
    const int warpM = wid & 1, warpN = wid >> 1;   // 2 x 4 warps, warp tile 32x32
    const int l4 = lane >> 2, q = lane & 3;
    const int b   = blockIdx.y >> 7;
    const int n0  = (blockIdx.y & 127) * 128;
    const int co0 = blockIdx.x * 64;

    const float* __restrict__ scv = g_scale[inLayer];
    const float* __restrict__ shv = g_shift[inLayer];
    const int nChunks = Ci >> 5;

    float acc[2][4][4];
#pragma unroll
    for (int mt = 0; mt < 2; mt++)
#pragma unroll
        for (int nt = 0; nt < 4; nt++)
#pragma unroll
            for (int j = 0; j < 4; j++) acc[mt][nt][j] = 0.f;

    // register staging for the in-flight chunk
    float4 aw[2];           // weights
    float4 bx0[2], bx1[2];  // activations (channel pair)

    auto ldg_chunk = [&](int ci0) {
#pragma unroll
        for (int i = 0; i < 2; i++) {
            int slot = i*256 + t;
            int co = slot >> 3, f4 = slot & 7;
            int cog = co0 + co;
            aw[i] = (cog < Co) ? *(const float4*)&W[(size_t)cog*wstride + ci0 + f4*4]
                               : make_float4(0.f, 0.f, 0.f, 0.f);
        }
#pragma unroll
        for (int i = 0; i < 2; i++) {
            int slot = i*256 + t;
            int kp = slot >> 5, f4 = slot & 31;
            int c0 = ci0 + kp*2;
            bx0[i] = *(const float4*)&X[((size_t)b*Ci + c0  )*NPTS + n0 + f4*4];
            bx1[i] = *(const float4*)&X[((size_t)b*Ci + c0+1)*NPTS + n0 + f4*4];
        }
    };

    auto sts_chunk = [&](int bufW, int ci0) {
        // A: [wh | wl]
#pragma unroll
        for (int i = 0; i < 2; i++) {
            int slot = i*256 + t;
            int co = slot >> 3, f4 = slot & 7;
            float4 w = aw[i];
            uint32_t h0 = cvt_h2(w.x, w.y);
            uint32_t h1 = cvt_h2(w.z, w.w);
            uint32_t l0 = cvt_h2(w.x - lo_h2(h0), w.y - hi_h2(h0));
            uint32_t l1 = cvt_h2(w.z - lo_h2(h1), w.w - hi_h2(h1));
            int wi = bufW + co*A_STR + f4*2;
            *(uint2*)&sm[wi]      = make_uint2(h0, h1);   // wh
            *(uint2*)&sm[wi + 16] = make_uint2(l0, l1);   // wl
        }
        // B: [xh | xl], BN+ReLU fused
#pragma unroll
        for (int i = 0; i < 2; i++) {
            int slot = i*256 + t;
            int kp = slot >> 5, f4 = slot & 31;
            int c0 = ci0 + kp*2;
            float s0 = scv[c0],   h0s = shv[c0];
            float s1 = scv[c0+1], h1s = shv[c0+1];
            float x0[4] = {bx0[i].x, bx0[i].y, bx0[i].z, bx0[i].w};
            float x1[4] = {bx1[i].x, bx1[i].y, bx1[i].z, bx1[i].w};
            uint32_t hw[4], lw[4];
#pragma unroll
            for (int j = 0; j < 4; j++) {
                float a0 = fmaxf(fmaf(x0[j], s0, h0s), 0.f);
                float a1 = fmaxf(fmaf(x1[j], s1, h1s), 0.f);
                uint32_t h = cvt_h2(a0, a1);
                hw[j] = h;
                lw[j] = cvt_h2(a0 - lo_h2(h), a1 - hi_h2(h));
            }
            int wi = bufW + B0_W + kp*B_STR + f4*4;
            *(uint4*)&sm[wi]            = make_uint4(hw[0], hw[1], hw[2], hw[3]); // xh
            *(uint4*)&sm[wi + 16*B_STR] = make_uint4(lw[0], lw[1], lw[2], lw[3]); // xl
        }
    };

    ldg_chunk(0);   // prologue

    for (int c = 0; c < nChunks; c++) {
        const int bufW = (c & 1) * SBUF_W;
        sts_chunk(bufW, c << 5);
        __syncthreads();                         // STS(c) visible to all warps
        if (c + 1 < nChunks) ldg_chunk((c+1) << 5);   // latency hidden by compute

        const uint32_t* Aw = sm + bufW;
        const uint32_t* Bx = sm + bufW + B0_W;
        const int aoff[6] = {0, 8, 0, 8, 16, 24};     // wh,wh | wh,wh | wl,wl
        const int boff[6] = {0, 8, 16, 24, 0, 8};     // xh,xh | xl,xl | xh,xh

#pragma unroll
        for (int kk = 0; kk < 6; kk++) {
            uint32_t af[2][4], bf[4][2];
#pragma unroll
            for (int mt = 0; mt < 2; mt++) {
                int base = (warpM*32 + mt*16 + l4) * A_STR + aoff[kk] + q;
                af[mt][0] = Aw[base];          af[mt][1] = Aw[base + 8*A_STR];
                af[mt][2] = Aw[base + 4];      af[mt][3] = Aw[base + 8*A_STR + 4];
            }
#pragma unroll
            for (int nt = 0; nt < 4; nt++) {
                int base = (boff[kk] + q) * B_STR + warpN*32 + nt*8 + l4;
                bf[nt][0] = Bx[base];  bf[nt][1] = Bx[base + 4*B_STR];
            }
#pragma unroll
            for (int mt = 0; mt < 2; mt++)
#pragma unroll
                for (int nt = 0; nt < 4; nt++)
                    mma_f16(acc[mt][nt], af[mt], bf[nt]);
        }
    }

    // ---- epilogue: store Y + fused per-row stats partials ----
    const int tileIdx = blockIdx.y * 4 + warpN;
#pragma unroll
    for (int mt = 0; mt < 2; mt++) {
        int row0 = co0 + warpM*32 + mt*16 + l4;
        int row1 = row0 + 8;
        float bs0 = 0.f, bs1 = 0.f;
        if (row0 < Co) bs0 = biasPerBatch ? bias[(size_t)b*Co + row0] : bias[row0];
        if (row1 < Co) bs1 = biasPerBatch ? bias[(size_t)b*Co + row1] : bias[row1];
        float s0 = 0.f, q0 = 0.f, s1 = 0.f, q1 = 0.f;
#pragma unroll
        for (int nt = 0; nt < 4; nt++) {
            int col = n0 + warpN*32 + nt*8 + q*2;
            float o0 = acc[mt][nt][0] + bs0, o1 = acc[mt][nt][1] + bs0;
            float o2 = acc[mt][nt][2] + bs1, o3 = acc[mt][nt][3] + bs1;
            s0 += o0 + o1;  q0 = fmaf(o0, o0, q0); q0 = fmaf(o1, o1, q0);
            s1 += o2 + o3;  q1 = fmaf(o2, o2, q1); q1 = fmaf(o3, o3, q1);
            if (row0 < Co)
                *(float2*)&Y[((size_t)b*Co + row0)*NPTS + col] = make_float2(o0, o1);
            if (row1 < Co)
                *(float2*)&Y[((size_t)b*Co + row1)*NPTS + col] = make_float2(o2, o3);
        }
        s0 += __shfl_xor_sync(0xffffffffu, s0, 1);  s0 += __shfl_xor_sync(0xffffffffu, s0, 2);
        q0 += __shfl_xor_sync(0xffffffffu, q0, 1);  q0 += __shfl_xor_sync(0xffffffffu, q0, 2);
        s1 += __shfl_xor_sync(0xffffffffu, s1, 1);  s1 += __shfl_xor_sync(0xffffffffu, s1, 2);
        q1 += __shfl_xor_sync(0xffffffffu, q1, 1);  q1 += __shfl_xor_sync(0xffffffffu, q1, 2);
        if (q == 0) {
            if (row0 < Co) {
                g_hsum[(size_t)row0*HPT + tileIdx] = s0;
                g_hsq [(size_t)row0*HPT + tileIdx] = q0;
            }
            if (row1 < Co) {
                g_hsum[(size_t)row1*HPT + tileIdx] = s1;
                g_hsq [(size_t)row1*HPT + tileIdx] = q1;
            }
        }
    }
}

// ---------------- finalize3: reduce HPT partials -> BN scale/shift ----------
__global__ void __launch_bounds__(256)
finalize3_kernel(const float* __restrict__ gamma,
                 const float* __restrict__ beta, int layer)
{
    const int c = blockIdx.x;
    const int t = threadIdx.x;
    float s = 0.f, q = 0.f;
#pragma unroll
    for (int i = 0; i < HPT/256; i++) {
        s += g_hsum[(size_t)c * HPT + i*256 + t];
        q += g_hsq [(size_t)c * HPT + i*256 + t];
    }
    __shared__ float ss[256], sq[256];
    ss[t] = s; sq[t] = q;
    __syncthreads();
    for (int st = 128; st > 0; st >>= 1) {
        if (t < st) { ss[t] += ss[t + st]; sq[t] += sq[t + st]; }
        __syncthreads();
    }
    if (t == 0) {
        float m   = ss[0] * (1.0f / BNTOT);
        float var = sq[0] * (1.0f / BNTOT) - m * m;
        float rstd = rsqrtf(var + 1e-5f);
        float scl  = gamma[c] * rstd;
        g_scale[layer][c] = scl;
        g_shift[layer][c] = fmaf(-m, scl, beta[c]);
    }
}

// =================== fp32 FFMA2 GEMM (layer 1 only) ==========================
__global__ void __launch_bounds__(256, 2)
gemm_kernel(const float* __restrict__ W, int wstride,
            const float* __restrict__ bias,
            const float* __restrict__ X, int Ci,
            float* __restrict__ Y, int Co)
{
    __shared__ __align__(16) ull   As2[16][65];
    __shared__ __align__(16) float Xs[16][256];

    const int t  = threadIdx.x;
    const int tn = t & 15;
    const int r  = t >> 4;
    const int tilesPerBatch = NPTS / 256;
    const int b   = blockIdx.y / tilesPerBatch;
    const int n0  = (blockIdx.y % tilesPerBatch) * 256;
    const int co0 = blockIdx.x * 64;

    ull acc2[4][8];
#pragma unroll
    for (int j = 0; j < 4; j++)
#pragma unroll
        for (int qq = 0; qq < 8; qq++) acc2[j][qq] = 0ull;

    const int nChunks = (Ci + 15) >> 4;
    float  wreg[4];
    float4 xreg[4];

    {
#pragma unroll
        for (int i = 0; i < 4; i++) {
            int lin = i*256 + t;
            int k = lin & 15, co = lin >> 4;
            int ci = k, cog = co0 + co;
            wreg[i] = (ci < Ci && cog < Co) ? W[(size_t)cog * wstride + ci] : 0.f;
        }
#pragma unroll
        for (int i = 0; i < 4; i++) {
            int fidx = i*256 + t;
            int k  = fidx >> 6;
            int n4 = fidx & 63;
            xreg[i] = (k < Ci) ? *(const float4*)&X[((size_t)b * Ci + k) * NPTS + n0 + n4*4]
                               : make_float4(0.f,0.f,0.f,0.f);
        }
    }

    for (int c = 0; c < nChunks; c++) {
        const int k0 = c << 4;
        if (c > 0) __syncthreads();
#pragma unroll
        for (int i = 0; i < 4; i++) {
            int lin = i*256 + t;
            int k = lin & 15, co = lin >> 4;
            float w = wreg[i];
            As2[k][co] = pack2(w, w);
        }
#pragma unroll
        for (int i = 0; i < 4; i++) {
            int fidx = i*256 + t;
            int k  = fidx >> 6;
            int n4 = fidx & 63;
            *(float4*)&Xs[k][n4*4] = xreg[i];
        }
        __syncthreads();

        if (c + 1 < nChunks) {
            const int k0n = k0 + 16;
#pragma unroll
            for (int i = 0; i < 4; i++) {
                int lin = i*256 + t;
                int k = lin & 15, co = lin >> 4;
                int ci = k0n + k, cog = co0 + co;
                wreg[i] = (ci < Ci && cog < Co) ? W[(size_t)cog * wstride + ci] : 0.f;
            }
#pragma unroll
            for (int i = 0; i < 4; i++) {
                int fidx = i*256 + t;
                int k  = fidx >> 6;
                int n4 = fidx & 63;
                int ci = k0n + k;
                xreg[i] = (ci < Ci) ? *(const float4*)&X[((size_t)b * Ci + ci) * NPTS + n0 + n4*4]
                                    : make_float4(0.f,0.f,0.f,0.f);
            }
        }

#pragma unroll
        for (int kk = 0; kk < 16; kk++) {
            ull a0 = As2[kk][r*4 + 0];
            ull a1 = As2[kk][r*4 + 1];
            ull a2 = As2[kk][r*4 + 2];
            ull a3 = As2[kk][r*4 + 3];
#pragma unroll
            for (int g = 0; g < 4; g++) {
                ulonglong2 xv = *(const ulonglong2*)&Xs[kk][g*64 + tn*4];
                acc2[0][g*2+0] = fma2(a0, xv.x, acc2[0][g*2+0]);
                acc2[0][g*2+1] = fma2(a0, xv.y, acc2[0][g*2+1]);
                acc2[1][g*2+0] = fma2(a1, xv.x, acc2[1][g*2+0]);
                acc2[1][g*2+1] = fma2(a1, xv.y, acc2[1][g*2+1]);
                acc2[2][g*2+0] = fma2(a2, xv.x, acc2[2][g*2+0]);
                acc2[2][g*2+1] = fma2(a2, xv.y, acc2[2][g*2+1]);
                acc2[3][g*2+0] = fma2(a3, xv.x, acc2[3][g*2+0]);
                acc2[3][g*2+1] = fma2(a3, xv.y, acc2[3][g*2+1]);
            }
        }
    }

    const int tile = blockIdx.y;
#pragma unroll
    for (int j = 0; j < 4; j++) {
        int cog = co0 + r*4 + j;
        bool valid = (cog < Co);
        float bs = valid ? bias[cog] : 0.f;
        float s = 0.f, q = 0.f;
        float* yr = valid ? &Y[((size_t)b * Co + cog) * NPTS + n0] : (float*)0;
#pragma unroll
        for (int g = 0; g < 4; g++) {
            float4 o;
            unpack2(acc2[j][g*2+0], o.x, o.y);
            unpack2(acc2[j][g*2+1], o.z, o.w);
            o.x += bs; o.y += bs; o.z += bs; o.w += bs;
            s += (o.x + o.y) + (o.z + o.w);
            q = fmaf(o.x, o.x, q); q = fmaf(o.y, o.y, q);
            q = fmaf(o.z, o.z, q); q = fmaf(o.w, o.w, q);
            if (valid) *(float4*)&yr[g*64 + tn*4] = o;
        }
#pragma unroll
        for (int off = 8; off; off >>= 1) {
            s += __shfl_down_sync(0xffffffffu, s, off, 16);
            q += __shfl_down_sync(0xffffffffu, q, off, 16);
        }
        if (tn == 0 && valid) {
            g_bsum[(size_t)cog * NTILE + tile] = s;
            g_bsq [(size_t)cog * NTILE + tile] = q;
        }
    }
}

// ---------------- finalize for L1 ([c][NTILE]) -------------------------------
__global__ void __launch_bounds__(256)
finalize_kernel(const float* __restrict__ gamma,
                const float* __restrict__ beta, int layer)
{
    const int c = blockIdx.x;
    const int t = threadIdx.x;
    float s = 0.f, q = 0.f;
#pragma unroll
    for (int i = 0; i < NTILE/256; i++) {
        s += g_bsum[(size_t)c * NTILE + i*256 + t];
        q += g_bsq [(size_t)c * NTILE + i*256 + t];
    }
    __shared__ float ss[256], sq[256];
    ss[t] = s; sq[t] = q;
    __syncthreads();
    for (int st = 128; st > 0; st >>= 1) {
        if (t < st) { ss[t] += ss[t + st]; sq[t] += sq[t + st]; }
        __syncthreads();
    }
    if (t == 0) {
        float m   = ss[0] * (1.0f / BNTOT);
        float var = sq[0] * (1.0f / BNTOT) - m * m;
        float rstd = rsqrtf(var + 1e-5f);
        float scl  = gamma[c] * rstd;
        g_scale[layer][c] = scl;
        g_shift[layer][c] = fmaf(-m, scl, beta[c]);
    }
}

// ---------------- dedicated L7: 128 -> 3, tanh ------------------------------
__global__ void __launch_bounds__(256)
conv7_kernel(const float* __restrict__ w7, const float* __restrict__ b7,
             const float* __restrict__ Y6, float* __restrict__ out)
{
    __shared__ float sw0[128], sw1[128], sw2[128], ssc[128], ssh[128];
    const int t = threadIdx.x;
    if (t < 128) {
        sw0[t] = w7[t]; sw1[t] = w7[128 + t]; sw2[t] = w7[256 + t];
        ssc[t] = g_scale[5][t]; ssh[t] = g_shift[5][t];
    }
    __syncthreads();

    const int idx = blockIdx.x * 256 + t;        // 65536 threads, 4 pts each
    const int b = idx >> 12;
    const int n = (idx & 4095) * 4;

    float4 a0 = make_float4(0.f,0.f,0.f,0.f);
    float4 a1 = a0, a2 = a0;
#pragma unroll 4
    for (int c = 0; c < 128; c++) {
        float4 v = *(const float4*)&Y6[((size_t)b*128 + c)*NPTS + n];
        float s = ssc[c], h = ssh[c];
        v.x = fmaxf(fmaf(v.x, s, h), 0.f);
        v.y = fmaxf(fmaf(v.y, s, h), 0.f);
        v.z = fmaxf(fmaf(v.z, s, h), 0.f);
        v.w = fmaxf(fmaf(v.w, s, h), 0.f);
        float w0 = sw0[c], w1 = sw1[c], w2 = sw2[c];
        a0.x = fmaf(w0, v.x, a0.x); a0.y = fmaf(w0, v.y, a0.y);
        a0.z = fmaf(w0, v.z, a0.z); a0.w = fmaf(w0, v.w, a0.w);
        a1.x = fmaf(w1, v.x, a1.x); a1.y = fmaf(w1, v.y, a1.y);
        a1.z = fmaf(w1, v.z, a1.z); a1.w = fmaf(w1, v.w, a1.w);
        a2.x = fmaf(w2, v.x, a2.x); a2.y = fmaf(w2, v.y, a2.y);
        a2.z = fmaf(w2, v.z, a2.z); a2.w = fmaf(w2, v.w, a2.w);
    }
    float b0 = b7[0], b1 = b7[1], b2 = b7[2];
    float4 o0 = make_float4(tanhf(a0.x+b0), tanhf(a0.y+b0), tanhf(a0.z+b0), tanhf(a0.w+b0));
    float4 o1 = make_float4(tanhf(a1.x+b1), tanhf(a1.y+b1), tanhf(a1.z+b1), tanhf(a1.w+b1));
    float4 o2 = make_float4(tanhf(a2.x+b2), tanhf(a2.y+b2), tanhf(a2.z+b2), tanhf(a2.w+b2));
    *(float4*)&out[((size_t)b*3 + 0)*NPTS + n] = o0;
    *(float4*)&out[((size_t)b*3 + 1)*NPTS + n] = o1;
    *(float4*)&out[((size_t)b*3 + 2)*NPTS + n] = o2;
}

// ---------------- SoftPool with smem row cache -------------------------------
__global__ void __launch_bounds__(256)
softpool_kernel(const float* __restrict__ w9, const float* __restrict__ b9)
{
    extern __shared__ float cache[];   // 16384 floats (64 KB)
    const int b = blockIdx.x >> 5;
    const int k = blockIdx.x & 31;
    const int t = threadIdx.x;

    __shared__ float sVal[256];
    __shared__ int   sIdx[256];
    __shared__ int   selIdx[16];

    const float sc = g_scale[2][k], sh = g_shift[2][k];
    const float* __restrict__ row = &g_y3[((size_t)b * 32 + k) * NPTS];

    for (int n = t; n < NPTS; n += 256) cache[n] = fmaf(row[n], sc, sh);
    __syncthreads();

    float lastV = -3.402823466e38f;
    int   lastI = -1;

    for (int p = 0; p < 16; p++) {
        float bv = 3.402823466e38f;
        int   bi = NPTS;
        for (int n = t; n < NPTS; n += 256) {
            float val = cache[n];
            bool elig = (val > lastV) || (val == lastV && n > lastI);
            if (elig && (val < bv || (val == bv && n < bi))) { bv = val; bi = n; }
        }
        sVal[t] = bv; sIdx[t] = bi;
        __syncthreads();
        for (int st = 128; st > 0; st >>= 1) {
            if (t < st) {
                float ov = sVal[t + st]; int oi = sIdx[t + st];
                if (ov < sVal[t] || (ov == sVal[t] && oi < sIdx[t])) { sVal[t] = ov; sIdx[t] = oi; }
            }
            __syncthreads();
        }
        lastV = sVal[0]; lastI = sIdx[0];
        if (t == 0) selIdx[p] = sIdx[0];
        __syncthreads();
    }

    float part = 0.f;
    for (int i = t; i < 512; i += 256) {
        int c = i >> 4, p = i & 15;
        int n = selIdx[p];
        float val = fmaf(g_y3[((size_t)b * 32 + c) * NPTS + n], g_scale[2][c], g_shift[2][c]);
        part = fmaf(w9[c * 16 + p], val, part);
    }
    sVal[t] = part;
    __syncthreads();
    for (int st = 128; st > 0; st >>= 1) {
        if (t < st) sVal[t] += sVal[t + st];
        __syncthreads();
    }
    if (t == 0) g_v[b * 32 + k] = sVal[0] + b9[0];
}

// ---------------- fold glob into conv4 bias ---------------------------------
__global__ void bias4_kernel(const float* __restrict__ w4, const float* __restrict__ b4)
{
    int idx = blockIdx.x * 256 + threadIdx.x;
    if (idx >= BATCH * 512) return;
    int b = idx >> 9, co = idx & 511;
    float s = b4[co];
#pragma unroll
    for (int k = 0; k < 32; k++) s = fmaf(w4[co * 96 + k], g_v[b * 32 + k], s);
    g_bias4[idx] = s;
}

// ---------------------------------------------------------------------------
extern "C" void kernel_launch(void* const* d_in, const int* in_sizes, int n_in,
                              void* d_out, int out_size)
{
    const float* x   = (const float*)d_in[0];
    const float* w1  = (const float*)d_in[1];  const float* b1  = (const float*)d_in[2];
    const float* g1  = (const float*)d_in[3];  const float* be1 = (const float*)d_in[4];
    const float* w2  = (const float*)d_in[5];  const float* b2  = (const float*)d_in[6];
    const float* g2  = (const float*)d_in[7];  const float* be2 = (const float*)d_in[8];
    const float* w3  = (const float*)d_in[9];  const float* b3  = (const float*)d_in[10];
    const float* g3  = (const float*)d_in[11]; const float* be3 = (const float*)d_in[12];
    const float* w9  = (const float*)d_in[13]; const float* b9  = (const float*)d_in[14];
    const float* w4  = (const float*)d_in[15]; const float* b4  = (const float*)d_in[16];
    const float* g4  = (const float*)d_in[17]; const float* be4 = (const float*)d_in[18];
    const float* w5  = (const float*)d_in[19]; const float* b5  = (const float*)d_in[20];
    const float* g5  = (const float*)d_in[21]; const float* be5 = (const float*)d_in[22];
    const float* w6  = (const float*)d_in[23]; const float* b6  = (const float*)d_in[24];
    const float* g6  = (const float*)d_in[25]; const float* be6 = (const float*)d_in[26];
    const float* w7  = (const float*)d_in[27]; const float* b7  = (const float*)d_in[28];

    float *y1, *y2, *y3, *y4, *y5, *y6, *bias4p;
    cudaGetSymbolAddress((void**)&y1, g_y1);
    cudaGetSymbolAddress((void**)&y2, g_y2);
    cudaGetSymbolAddress((void**)&y3, g_y3);
    cudaGetSymbolAddress((void**)&y4, g_y4);
    cudaGetSymbolAddress((void**)&y5, g_y5);
    cudaGetSymbolAddress((void**)&y6, g_y6);
    cudaGetSymbolAddress((void**)&bias4p, g_bias4);

    const int SMEM = 2 * SBUF_W * 4;   // 53248 B
    cudaFuncSetAttribute(hmma_gemm_kernel, cudaFuncAttributeMaxDynamicSharedMemorySize, SMEM);
    const int SPSM = NPTS * 4;         // 65536 B
    cudaFuncSetAttribute(softpool_kernel, cudaFuncAttributeMaxDynamicSharedMemorySize, SPSM);

    const dim3 blk(256);

    // L1: 4 -> 64 (fp32, fused stats)
    gemm_kernel<<<dim3(1, NTILE), blk>>>(w1, 4, b1, x, 4, y1, 64);
    finalize_kernel<<<64, 256>>>(g1, be1, 0);

    // L2: 64 -> 128 (HMMA, fused stats)
    hmma_gemm_kernel<<<dim3(2, 2048), blk, SMEM>>>(w2, 64, b2, 0, y1, 64, 0, y2, 128);
    finalize3_kernel<<<128, 256>>>(g2, be2, 1);

    // L3: 128 -> 32 (HMMA)
    hmma_gemm_kernel<<<dim3(1, 2048), blk, SMEM>>>(w3, 128, b3, 0, y2, 128, 1, y3, 32);
    finalize3_kernel<<<32, 256>>>(g3, be3, 2);

    // SoftPool + fold glob into conv4 bias
    softpool_kernel<<<512, 256, SPSM>>>(w9, b9);
    bias4_kernel<<<32, 256>>>(w4, b4);

    // L4: 64 -> 512 on h1 (HMMA, per-batch bias, glob folded, weight rows offset 32)
    hmma_gemm_kernel<<<dim3(8, 2048), blk, SMEM>>>(w4 + 32, 96, bias4p, 1, y1, 64, 0, y4, 512);
    finalize3_kernel<<<512, 256>>>(g4, be4, 3);

    // L5: 512 -> 256 (HMMA)
    hmma_gemm_kernel<<<dim3(4, 2048), blk, SMEM>>>(w5, 512, b5, 0, y4, 512, 3, y5, 256);
    finalize3_kernel<<<256, 256>>>(g5, be5, 4);

    // L6: 256 -> 128 (HMMA)
    hmma_gemm_kernel<<<dim3(2, 2048), blk, SMEM>>>(w6, 256, b6, 0, y5, 256, 4, y6, 128);
    finalize3_kernel<<<128, 256>>>(g6, be6, 5);

    // L7: 128 -> 3, tanh, dedicated kernel, straight to output
    conv7_kernel<<<BNTOT/4/256, blk>>>(w7, b7, y6, (float*)d_out);
}

// round 9
// speedup vs baseline: 2.6616x; 1.0143x over previous
#include <cuda_runtime.h>
#include <cuda_fp16.h>
#include <math.h>
#include <stdint.h>

#define BATCH 16
#define NPTS  16384
#define BNTOT (BATCH*NPTS)
#define NTILE (BNTOT/256)   // 1024 column tiles (fp32 gemm path)
#define HPT   8192          // hmma stats partials per channel

typedef unsigned long long ull;

// ---------------- packed f32x2 / fp16 helpers --------------------------------
__device__ __forceinline__ ull pack2(float lo, float hi) {
    ull r; asm("mov.b64 %0, {%1, %2};" : "=l"(r) : "f"(lo), "f"(hi)); return r;
}
__device__ __forceinline__ ull fma2(ull a, ull b, ull c) {
    ull d; asm("fma.rn.f32x2 %0, %1, %2, %3;" : "=l"(d) : "l"(a), "l"(b), "l"(c)); return d;
}
__device__ __forceinline__ void unpack2(ull v, float& lo, float& hi) {
    asm("mov.b64 {%0, %1}, %2;" : "=f"(lo), "=f"(hi) : "l"(v));
}
__device__ __forceinline__ uint32_t cvt_h2(float lo, float hi) {
    uint32_t r;
    asm("cvt.rn.satfinite.f16x2.f32 %0, %1, %2;" : "=r"(r) : "f"(hi), "f"(lo));
    return r;
}
__device__ __forceinline__ float lo_h2(uint32_t h) {
    __half2 hh = *reinterpret_cast<const __half2*>(&h);
    return __low2float(hh);
}
__device__ __forceinline__ float hi_h2(uint32_t h) {
    __half2 hh = *reinterpret_cast<const __half2*>(&h);
    return __high2float(hh);
}
__device__ __forceinline__ void mma_f16(float d[4], const uint32_t a[4], const uint32_t b[2]) {
    asm volatile("mma.sync.aligned.m16n8k16.row.col.f32.f16.f16.f32 "
        "{%0,%1,%2,%3}, {%4,%5,%6,%7}, {%8,%9}, {%0,%1,%2,%3};"
        : "+f"(d[0]), "+f"(d[1]), "+f"(d[2]), "+f"(d[3])
        : "r"(a[0]), "r"(a[1]), "r"(a[2]), "r"(a[3]), "r"(b[0]), "r"(b[1]));
}
// canonical A-fragment load: 16x16 f16 tile, rows contiguous in smem
__device__ __forceinline__ void ldsm_x4(uint32_t r[4], const uint32_t* p) {
    uint32_t a = (uint32_t)__cvta_generic_to_shared(p);
    asm volatile("ldmatrix.sync.aligned.m8n8.x4.shared.b16 {%0,%1,%2,%3}, [%4];"
        : "=r"(r[0]), "=r"(r[1]), "=r"(r[2]), "=r"(r[3]) : "r"(a));
}

// ---------------- scratch (device globals) ----------------------------------
__device__ float g_y1[(size_t)BATCH*64*NPTS];
__device__ float g_y2[(size_t)BATCH*128*NPTS];
__device__ float g_y3[(size_t)BATCH*32*NPTS];
__device__ float g_y4[(size_t)BATCH*512*NPTS];
__device__ float g_y5[(size_t)BATCH*256*NPTS];
__device__ float g_y6[(size_t)BATCH*128*NPTS];
__device__ float g_bsum[(size_t)64*NTILE];      // L1 fused stats [c][tile]
__device__ float g_bsq [(size_t)64*NTILE];
__device__ float g_hsum[(size_t)512*HPT];       // hmma fused stats [c][tile*4+warpN]
__device__ float g_hsq [(size_t)512*HPT];
__device__ float g_scale[6][512];
__device__ float g_shift[6][512];
__device__ float g_v[BATCH*32];
__device__ float g_bias4[BATCH*512];

// =================== HMMA fp16 3-term-split GEMM (layers 2-6) ================
// Per 32-channel chunk: A = [wh(16w) | wl(16w)], B = [xh(16r) | xl(16r)].
// Mainloop: per k16-group, load Ah/Al via ldmatrix.x4 and Bh/Bl via LDS once,
// then issue Ah*Bh + Ah*Bl + Al*Bh (fragment reuse, 3-term split).
#define A_STR  36               // 32 data words + 4 pad
#define B_STR  136              // 128 data words + 8 pad
#define B0_W   2304             // A region = 64*36 words
#define SBUF_W 6656             // + B region 32*136 = 4352 words (26.6 KB/buf)

__global__ void __launch_bounds__(256, 2)
hmma_gemm_kernel(const float* __restrict__ W, int wstride,
                 const float* __restrict__ bias, int biasPerBatch,
                 const float* __restrict__ X, int Ci, int inLayer,
                 float* __restrict__ Y, int Co)
{
    extern __shared__ uint32_t sm[];
    const int t    = threadIdx.x;
    const int lane = t & 31, wid = t >> 5;
    const int warpM = wid & 1, warpN = wid >> 1;   // 2 x 4 warps, warp tile 32x32
    const int l4 = lane >> 2, q = lane & 3;
    const int b   = blockIdx.y >> 7;
    const int n0  = (blockIdx.y & 127) * 128;
    const int co0 = blockIdx.x * 64;

    const float* __restrict__ scv = g_scale[inLayer];
    const float* __restrict__ shv = g_shift[inLayer];
    const int nChunks = Ci >> 5;

    float acc[2][4][4];
#pragma unroll
    for (int mt = 0; mt < 2; mt++)
#pragma unroll
        for (int nt = 0; nt < 4; nt++)
#pragma unroll
            for (int j = 0; j < 4; j++) acc[mt][nt][j] = 0.f;

    // register staging for the in-flight chunk
    float4 aw[2];           // weights
    float4 bx0[2], bx1[2];  // activations (channel pair)

    auto ldg_chunk = [&](int ci0) {
#pragma unroll
        for (int i = 0; i < 2; i++) {
            int slot = i*256 + t;
            int co = slot >> 3, f4 = slot & 7;
            int cog = co0 + co;
            aw[i] = (cog < Co) ? *(const float4*)&W[(size_t)cog*wstride + ci0 + f4*4]
                               : make_float4(0.f, 0.f, 0.f, 0.f);
        }
#pragma unroll
        for (int i = 0; i < 2; i++) {
            int slot = i*256 + t;
            int kp = slot >> 5, f4 = slot & 31;
            int c0 = ci0 + kp*2;
            bx0[i] = *(const float4*)&X[((size_t)b*Ci + c0  )*NPTS + n0 + f4*4];
            bx1[i] = *(const float4*)&X[((size_t)b*Ci + c0+1)*NPTS + n0 + f4*4];
        }
    };

    auto sts_chunk = [&](int bufW, int ci0) {
        // A: [wh | wl]
#pragma unroll
        for (int i = 0; i < 2; i++) {
            int slot = i*256 + t;
            int co = slot >> 3, f4 = slot & 7;
            float4 w = aw[i];
            uint32_t h0 = cvt_h2(w.x, w.y);
            uint32_t h1 = cvt_h2(w.z, w.w);
            uint32_t l0 = cvt_h2(w.x - lo_h2(h0), w.y - hi_h2(h0));
            uint32_t l1 = cvt_h2(w.z - lo_h2(h1), w.w - hi_h2(h1));
            int wi = bufW + co*A_STR + f4*2;
            *(uint2*)&sm[wi]      = make_uint2(h0, h1);   // wh
            *(uint2*)&sm[wi + 16] = make_uint2(l0, l1);   // wl
        }
        // B: [xh | xl], BN+ReLU fused
#pragma unroll
        for (int i = 0; i < 2; i++) {
            int slot = i*256 + t;
            int kp = slot >> 5, f4 = slot & 31;
            int c0 = ci0 + kp*2;
            float s0 = scv[c0],   h0s = shv[c0];
            float s1 = scv[c0+1], h1s = shv[c0+1];
            float x0[4] = {bx0[i].x, bx0[i].y, bx0[i].z, bx0[i].w};
            float x1[4] = {bx1[i].x, bx1[i].y, bx1[i].z, bx1[i].w};
            uint32_t hw[4], lw[4];
#pragma unroll
            for (int j = 0; j < 4; j++) {
                float a0 = fmaxf(fmaf(x0[j], s0, h0s), 0.f);
                float a1 = fmaxf(fmaf(x1[j], s1, h1s), 0.f);
                uint32_t h = cvt_h2(a0, a1);
                hw[j] = h;
                lw[j] = cvt_h2(a0 - lo_h2(h), a1 - hi_h2(h));
            }
            int wi = bufW + B0_W + kp*B_STR + f4*4;
            *(uint4*)&sm[wi]            = make_uint4(hw[0], hw[1], hw[2], hw[3]); // xh
            *(uint4*)&sm[wi + 16*B_STR] = make_uint4(lw[0], lw[1], lw[2], lw[3]); // xl
        }
    };

    ldg_chunk(0);   // prologue

    // ldmatrix addressing (constant per thread): rows 0-15 -> lanes 0-15,
    // k-half +8 -> lanes 16-31.
    const int lrow = lane & 15;
    const int lkw  = (lane >> 4) * 4;   // word offset for k+8 half

    for (int c = 0; c < nChunks; c++) {
        const int bufW = (c & 1) * SBUF_W;
        sts_chunk(bufW, c << 5);
        __syncthreads();                         // STS(c) visible to all warps
        if (c + 1 < nChunks) ldg_chunk((c+1) << 5);   // latency hidden by compute

        const uint32_t* Aw = sm + bufW;
        const uint32_t* Bx = sm + bufW + B0_W;

#pragma unroll
        for (int kg = 0; kg < 2; kg++) {         // k16 group within the chunk
            uint32_t ah[2][4], al[2][4];
#pragma unroll
            for (int mt = 0; mt < 2; mt++) {
                const uint32_t* base =
                    Aw + (warpM*32 + mt*16 + lrow) * A_STR + kg*8 + lkw;
                ldsm_x4(ah[mt], base);           // wh fragment
                ldsm_x4(al[mt], base + 16);      // wl fragment
            }
            uint32_t bh[4][2], bl[4][2];
#pragma unroll
            for (int nt = 0; nt < 4; nt++) {
                int base = (kg*8 + q) * B_STR + warpN*32 + nt*8 + l4;
                bh[nt][0] = Bx[base];             bh[nt][1] = Bx[base + 4*B_STR];
                bl[nt][0] = Bx[base + 16*B_STR];  bl[nt][1] = Bx[base + 20*B_STR];
            }
#pragma unroll
            for (int mt = 0; mt < 2; mt++)
#pragma unroll
                for (int nt = 0; nt < 4; nt++) {
                    mma_f16(acc[mt][nt], ah[mt], bh[nt]);
                    mma_f16(acc[mt][nt], ah[mt], bl[nt]);
                    mma_f16(acc[mt][nt], al[mt], bh[nt]);
                }
        }
    }

    // ---- epilogue: store Y + fused per-row stats partials ----
    const int tileIdx = blockIdx.y * 4 + warpN;
#pragma unroll
    for (int mt = 0; mt < 2; mt++) {
        int row0 = co0 + warpM*32 + mt*16 + l4;
        int row1 = row0 + 8;
        float bs0 = 0.f, bs1 = 0.f;
        if (row0 < Co) bs0 = biasPerBatch ? bias[(size_t)b*Co + row0] : bias[row0];
        if (row1 < Co) bs1 = biasPerBatch ? bias[(size_t)b*Co + row1] : bias[row1];
        float s0 = 0.f, q0 = 0.f, s1 = 0.f, q1 = 0.f;
#pragma unroll
        for (int nt = 0; nt < 4; nt++) {
            int col = n0 + warpN*32 + nt*8 + q*2;
            float o0 = acc[mt][nt][0] + bs0, o1 = acc[mt][nt][1] + bs0;
            float o2 = acc[mt][nt][2] + bs1, o3 = acc[mt][nt][3] + bs1;
            s0 += o0 + o1;  q0 = fmaf(o0, o0, q0); q0 = fmaf(o1, o1, q0);
            s1 += o2 + o3;  q1 = fmaf(o2, o2, q1); q1 = fmaf(o3, o3, q1);
            if (row0 < Co)
                *(float2*)&Y[((size_t)b*Co + row0)*NPTS + col] = make_float2(o0, o1);
            if (row1 < Co)
                *(float2*)&Y[((size_t)b*Co + row1)*NPTS + col] = make_float2(o2, o3);
        }
        s0 += __shfl_xor_sync(0xffffffffu, s0, 1);  s0 += __shfl_xor_sync(0xffffffffu, s0, 2);
        q0 += __shfl_xor_sync(0xffffffffu, q0, 1);  q0 += __shfl_xor_sync(0xffffffffu, q0, 2);
        s1 += __shfl_xor_sync(0xffffffffu, s1, 1);  s1 += __shfl_xor_sync(0xffffffffu, s1, 2);
        q1 += __shfl_xor_sync(0xffffffffu, q1, 1);  q1 += __shfl_xor_sync(0xffffffffu, q1, 2);
        if (q == 0) {
            if (row0 < Co) {
                g_hsum[(size_t)row0*HPT + tileIdx] = s0;
                g_hsq [(size_t)row0*HPT + tileIdx] = q0;
            }
            if (row1 < Co) {
                g_hsum[(size_t)row1*HPT + tileIdx] = s1;
                g_hsq [(size_t)row1*HPT + tileIdx] = q1;
            }
        }
    }
}

// ---------------- finalize3: reduce HPT partials -> BN scale/shift ----------
__global__ void __launch_bounds__(256)
finalize3_kernel(const float* __restrict__ gamma,
                 const float* __restrict__ beta, int layer)
{
    const int c = blockIdx.x;
    const int t = threadIdx.x;
    float s = 0.f, q = 0.f;
#pragma unroll
    for (int i = 0; i < HPT/256; i++) {
        s += g_hsum[(size_t)c * HPT + i*256 + t];
        q += g_hsq [(size_t)c * HPT + i*256 + t];
    }
    __shared__ float ss[256], sq[256];
    ss[t] = s; sq[t] = q;
    __syncthreads();
    for (int st = 128; st > 0; st >>= 1) {
        if (t < st) { ss[t] += ss[t + st]; sq[t] += sq[t + st]; }
        __syncthreads();
    }
    if (t == 0) {
        float m   = ss[0] * (1.0f / BNTOT);
        float var = sq[0] * (1.0f / BNTOT) - m * m;
        float rstd = rsqrtf(var + 1e-5f);
        float scl  = gamma[c] * rstd;
        g_scale[layer][c] = scl;
        g_shift[layer][c] = fmaf(-m, scl, beta[c]);
    }
}

// =================== fp32 FFMA2 GEMM (layer 1 only) ==========================
__global__ void __launch_bounds__(256, 2)
gemm_kernel(const float* __restrict__ W, int wstride,
            const float* __restrict__ bias,
            const float* __restrict__ X, int Ci,
            float* __restrict__ Y, int Co)
{
    __shared__ __align__(16) ull   As2[16][65];
    __shared__ __align__(16) float Xs[16][256];

    const int t  = threadIdx.x;
    const int tn = t & 15;
    const int r  = t >> 4;
    const int tilesPerBatch = NPTS / 256;
    const int b   = blockIdx.y / tilesPerBatch;
    const int n0  = (blockIdx.y % tilesPerBatch) * 256;
    const int co0 = blockIdx.x * 64;

    ull acc2[4][8];
#pragma unroll
    for (int j = 0; j < 4; j++)
#pragma unroll
        for (int qq = 0; qq < 8; qq++) acc2[j][qq] = 0ull;

    const int nChunks = (Ci + 15) >> 4;
    float  wreg[4];
    float4 xreg[4];

    {
#pragma unroll
        for (int i = 0; i < 4; i++) {
            int lin = i*256 + t;
            int k = lin & 15, co = lin >> 4;
            int ci = k, cog = co0 + co;
            wreg[i] = (ci < Ci && cog < Co) ? W[(size_t)cog * wstride + ci] : 0.f;
        }
#pragma unroll
        for (int i = 0; i < 4; i++) {
            int fidx = i*256 + t;
            int k  = fidx >> 6;
            int n4 = fidx & 63;
            xreg[i] = (k < Ci) ? *(const float4*)&X[((size_t)b * Ci + k) * NPTS + n0 + n4*4]
                               : make_float4(0.f,0.f,0.f,0.f);
        }
    }

    for (int c = 0; c < nChunks; c++) {
        const int k0 = c << 4;
        if (c > 0) __syncthreads();
#pragma unroll
        for (int i = 0; i < 4; i++) {
            int lin = i*256 + t;
            int k = lin & 15, co = lin >> 4;
            float w = wreg[i];
            As2[k][co] = pack2(w, w);
        }
#pragma unroll
        for (int i = 0; i < 4; i++) {
            int fidx = i*256 + t;
            int k  = fidx >> 6;
            int n4 = fidx & 63;
            *(float4*)&Xs[k][n4*4] = xreg[i];
        }
        __syncthreads();

        if (c + 1 < nChunks) {
            const int k0n = k0 + 16;
#pragma unroll
            for (int i = 0; i < 4; i++) {
                int lin = i*256 + t;
                int k = lin & 15, co = lin >> 4;
                int ci = k0n + k, cog = co0 + co;
                wreg[i] = (ci < Ci && cog < Co) ? W[(size_t)cog * wstride + ci] : 0.f;
            }
#pragma unroll
            for (int i = 0; i < 4; i++) {
                int fidx = i*256 + t;
                int k  = fidx >> 6;
                int n4 = fidx & 63;
                int ci = k0n + k;
                xreg[i] = (ci < Ci) ? *(const float4*)&X[((size_t)b * Ci + ci) * NPTS + n0 + n4*4]
                                    : make_float4(0.f,0.f,0.f,0.f);
            }
        }

#pragma unroll
        for (int kk = 0; kk < 16; kk++) {
            ull a0 = As2[kk][r*4 + 0];
            ull a1 = As2[kk][r*4 + 1];
            ull a2 = As2[kk][r*4 + 2];
            ull a3 = As2[kk][r*4 + 3];
#pragma unroll
            for (int g = 0; g < 4; g++) {
                ulonglong2 xv = *(const ulonglong2*)&Xs[kk][g*64 + tn*4];
                acc2[0][g*2+0] = fma2(a0, xv.x, acc2[0][g*2+0]);
                acc2[0][g*2+1] = fma2(a0, xv.y, acc2[0][g*2+1]);
                acc2[1][g*2+0] = fma2(a1, xv.x, acc2[1][g*2+0]);
                acc2[1][g*2+1] = fma2(a1, xv.y, acc2[1][g*2+1]);
                acc2[2][g*2+0] = fma2(a2, xv.x, acc2[2][g*2+0]);
                acc2[2][g*2+1] = fma2(a2, xv.y, acc2[2][g*2+1]);
                acc2[3][g*2+0] = fma2(a3, xv.x, acc2[3][g*2+0]);
                acc2[3][g*2+1] = fma2(a3, xv.y, acc2[3][g*2+1]);
            }
        }
    }

    const int tile = blockIdx.y;
#pragma unroll
    for (int j = 0; j < 4; j++) {
        int cog = co0 + r*4 + j;
        bool valid = (cog < Co);
        float bs = valid ? bias[cog] : 0.f;
        float s = 0.f, q = 0.f;
        float* yr = valid ? &Y[((size_t)b * Co + cog) * NPTS + n0] : (float*)0;
#pragma unroll
        for (int g = 0; g < 4; g++) {
            float4 o;
            unpack2(acc2[j][g*2+0], o.x, o.y);
            unpack2(acc2[j][g*2+1], o.z, o.w);
            o.x += bs; o.y += bs; o.z += bs; o.w += bs;
            s += (o.x + o.y) + (o.z + o.w);
            q = fmaf(o.x, o.x, q); q = fmaf(o.y, o.y, q);
            q = fmaf(o.z, o.z, q); q = fmaf(o.w, o.w, q);
            if (valid) *(float4*)&yr[g*64 + tn*4] = o;
        }
#pragma unroll
        for (int off = 8; off; off >>= 1) {
            s += __shfl_down_sync(0xffffffffu, s, off, 16);
            q += __shfl_down_sync(0xffffffffu, q, off, 16);
        }
        if (tn == 0 && valid) {
            g_bsum[(size_t)cog * NTILE + tile] = s;
            g_bsq [(size_t)cog * NTILE + tile] = q;
        }
    }
}

// ---------------- finalize for L1 ([c][NTILE]) -------------------------------
__global__ void __launch_bounds__(256)
finalize_kernel(const float* __restrict__ gamma,
                const float* __restrict__ beta, int layer)
{
    const int c = blockIdx.x;
    const int t = threadIdx.x;
    float s = 0.f, q = 0.f;
#pragma unroll
    for (int i = 0; i < NTILE/256; i++) {
        s += g_bsum[(size_t)c * NTILE + i*256 + t];
        q += g_bsq [(size_t)c * NTILE + i*256 + t];
    }
    __shared__ float ss[256], sq[256];
    ss[t] = s; sq[t] = q;
    __syncthreads();
    for (int st = 128; st > 0; st >>= 1) {
        if (t < st) { ss[t] += ss[t + st]; sq[t] += sq[t + st]; }
        __syncthreads();
    }
    if (t == 0) {
        float m   = ss[0] * (1.0f / BNTOT);
        float var = sq[0] * (1.0f / BNTOT) - m * m;
        float rstd = rsqrtf(var + 1e-5f);
        float scl  = gamma[c] * rstd;
        g_scale[layer][c] = scl;
        g_shift[layer][c] = fmaf(-m, scl, beta[c]);
    }
}

// ---------------- dedicated L7: 128 -> 3, tanh ------------------------------
__global__ void __launch_bounds__(256)
conv7_kernel(const float* __restrict__ w7, const float* __restrict__ b7,
             const float* __restrict__ Y6, float* __restrict__ out)
{
    __shared__ float sw0[128], sw1[128], sw2[128], ssc[128], ssh[128];
    const int t = threadIdx.x;
    if (t < 128) {
        sw0[t] = w7[t]; sw1[t] = w7[128 + t]; sw2[t] = w7[256 + t];
        ssc[t] = g_scale[5][t]; ssh[t] = g_shift[5][t];
    }
    __syncthreads();

    const int idx = blockIdx.x * 256 + t;        // 65536 threads, 4 pts each
    const int b = idx >> 12;
    const int n = (idx & 4095) * 4;

    float4 a0 = make_float4(0.f,0.f,0.f,0.f);
    float4 a1 = a0, a2 = a0;
#pragma unroll 4
    for (int c = 0; c < 128; c++) {
        float4 v = *(const float4*)&Y6[((size_t)b*128 + c)*NPTS + n];
        float s = ssc[c], h = ssh[c];
        v.x = fmaxf(fmaf(v.x, s, h), 0.f);
        v.y = fmaxf(fmaf(v.y, s, h), 0.f);
        v.z = fmaxf(fmaf(v.z, s, h), 0.f);
        v.w = fmaxf(fmaf(v.w, s, h), 0.f);
        float w0 = sw0[c], w1 = sw1[c], w2 = sw2[c];
        a0.x = fmaf(w0, v.x, a0.x); a0.y = fmaf(w0, v.y, a0.y);
        a0.z = fmaf(w0, v.z, a0.z); a0.w = fmaf(w0, v.w, a0.w);
        a1.x = fmaf(w1, v.x, a1.x); a1.y = fmaf(w1, v.y, a1.y);
        a1.z = fmaf(w1, v.z, a1.z); a1.w = fmaf(w1, v.w, a1.w);
        a2.x = fmaf(w2, v.x, a2.x); a2.y = fmaf(w2, v.y, a2.y);
        a2.z = fmaf(w2, v.z, a2.z); a2.w = fmaf(w2, v.w, a2.w);
    }
    float b0 = b7[0], b1 = b7[1], b2 = b7[2];
    float4 o0 = make_float4(tanhf(a0.x+b0), tanhf(a0.y+b0), tanhf(a0.z+b0), tanhf(a0.w+b0));
    float4 o1 = make_float4(tanhf(a1.x+b1), tanhf(a1.y+b1), tanhf(a1.z+b1), tanhf(a1.w+b1));
    float4 o2 = make_float4(tanhf(a2.x+b2), tanhf(a2.y+b2), tanhf(a2.z+b2), tanhf(a2.w+b2));
    *(float4*)&out[((size_t)b*3 + 0)*NPTS + n] = o0;
    *(float4*)&out[((size_t)b*3 + 1)*NPTS + n] = o1;
    *(float4*)&out[((size_t)b*3 + 2)*NPTS + n] = o2;
}

// ---------------- SoftPool with smem row cache -------------------------------
__global__ void __launch_bounds__(256)
softpool_kernel(const float* __restrict__ w9, const float* __restrict__ b9)
{
    extern __shared__ float cache[];   // 16384 floats (64 KB)
    const int b = blockIdx.x >> 5;
    const int k = blockIdx.x & 31;
    const int t = threadIdx.x;

    __shared__ float sVal[256];
    __shared__ int   sIdx[256];
    __shared__ int   selIdx[16];

    const float sc = g_scale[2][k], sh = g_shift[2][k];
    const float* __restrict__ row = &g_y3[((size_t)b * 32 + k) * NPTS];

    for (int n = t; n < NPTS; n += 256) cache[n] = fmaf(row[n], sc, sh);
    __syncthreads();

    float lastV = -3.402823466e38f;
    int   lastI = -1;

    for (int p = 0; p < 16; p++) {
        float bv = 3.402823466e38f;
        int   bi = NPTS;
        for (int n = t; n < NPTS; n += 256) {
            float val = cache[n];
            bool elig = (val > lastV) || (val == lastV && n > lastI);
            if (elig && (val < bv || (val == bv && n < bi))) { bv = val; bi = n; }
        }
        sVal[t] = bv; sIdx[t] = bi;
        __syncthreads();
        for (int st = 128; st > 0; st >>= 1) {
            if (t < st) {
                float ov = sVal[t + st]; int oi = sIdx[t + st];
                if (ov < sVal[t] || (ov == sVal[t] && oi < sIdx[t])) { sVal[t] = ov; sIdx[t] = oi; }
            }
            __syncthreads();
        }
        lastV = sVal[0]; lastI = sIdx[0];
        if (t == 0) selIdx[p] = sIdx[0];
        __syncthreads();
    }

    float part = 0.f;
    for (int i = t; i < 512; i += 256) {
        int c = i >> 4, p = i & 15;
        int n = selIdx[p];
        float val = fmaf(g_y3[((size_t)b * 32 + c) * NPTS + n], g_scale[2][c], g_shift[2][c]);
        part = fmaf(w9[c * 16 + p], val, part);
    }
    sVal[t] = part;
    __syncthreads();
    for (int st = 128; st > 0; st >>= 1) {
        if (t < st) sVal[t] += sVal[t + st];
        __syncthreads();
    }
    if (t == 0) g_v[b * 32 + k] = sVal[0] + b9[0];
}

// ---------------- fold glob into conv4 bias ---------------------------------
__global__ void bias4_kernel(const float* __restrict__ w4, const float* __restrict__ b4)
{
    int idx = blockIdx.x * 256 + threadIdx.x;
    if (idx >= BATCH * 512) return;
    int b = idx >> 9, co = idx & 511;
    float s = b4[co];
#pragma unroll
    for (int k = 0; k < 32; k++) s = fmaf(w4[co * 96 + k], g_v[b * 32 + k], s);
    g_bias4[idx] = s;
}

// ---------------------------------------------------------------------------
extern "C" void kernel_launch(void* const* d_in, const int* in_sizes, int n_in,
                              void* d_out, int out_size)
{
    const float* x   = (const float*)d_in[0];
    const float* w1  = (const float*)d_in[1];  const float* b1  = (const float*)d_in[2];
    const float* g1  = (const float*)d_in[3];  const float* be1 = (const float*)d_in[4];
    const float* w2  = (const float*)d_in[5];  const float* b2  = (const float*)d_in[6];
    const float* g2  = (const float*)d_in[7];  const float* be2 = (const float*)d_in[8];
    const float* w3  = (const float*)d_in[9];  const float* b3  = (const float*)d_in[10];
    const float* g3  = (const float*)d_in[11]; const float* be3 = (const float*)d_in[12];
    const float* w9  = (const float*)d_in[13]; const float* b9  = (const float*)d_in[14];
    const float* w4  = (const float*)d_in[15]; const float* b4  = (const float*)d_in[16];
    const float* g4  = (const float*)d_in[17]; const float* be4 = (const float*)d_in[18];
    const float* w5  = (const float*)d_in[19]; const float* b5  = (const float*)d_in[20];
    const float* g5  = (const float*)d_in[21]; const float* be5 = (const float*)d_in[22];
    const float* w6  = (const float*)d_in[23]; const float* b6  = (const float*)d_in[24];
    const float* g6  = (const float*)d_in[25]; const float* be6 = (const float*)d_in[26];
    const float* w7  = (const float*)d_in[27]; const float* b7  = (const float*)d_in[28];

    float *y1, *y2, *y3, *y4, *y5, *y6, *bias4p;
    cudaGetSymbolAddress((void**)&y1, g_y1);
    cudaGetSymbolAddress((void**)&y2, g_y2);
    cudaGetSymbolAddress((void**)&y3, g_y3);
    cudaGetSymbolAddress((void**)&y4, g_y4);
    cudaGetSymbolAddress((void**)&y5, g_y5);
    cudaGetSymbolAddress((void**)&y6, g_y6);
    cudaGetSymbolAddress((void**)&bias4p, g_bias4);

    const int SMEM = 2 * SBUF_W * 4;   // 53248 B
    cudaFuncSetAttribute(hmma_gemm_kernel, cudaFuncAttributeMaxDynamicSharedMemorySize, SMEM);
    const int SPSM = NPTS * 4;         // 65536 B
    cudaFuncSetAttribute(softpool_kernel, cudaFuncAttributeMaxDynamicSharedMemorySize, SPSM);

    const dim3 blk(256);

    // L1: 4 -> 64 (fp32, fused stats)
    gemm_kernel<<<dim3(1, NTILE), blk>>>(w1, 4, b1, x, 4, y1, 64);
    finalize_kernel<<<64, 256>>>(g1, be1, 0);

    // L2: 64 -> 128 (HMMA, fused stats)
    hmma_gemm_kernel<<<dim3(2, 2048), blk, SMEM>>>(w2, 64, b2, 0, y1, 64, 0, y2, 128);
    finalize3_kernel<<<128, 256>>>(g2, be2, 1);

    // L3: 128 -> 32 (HMMA)
    hmma_gemm_kernel<<<dim3(1, 2048), blk, SMEM>>>(w3, 128, b3, 0, y2, 128, 1, y3, 32);
    finalize3_kernel<<<32, 256>>>(g3, be3, 2);

    // SoftPool + fold glob into conv4 bias
    softpool_kernel<<<512, 256, SPSM>>>(w9, b9);
    bias4_kernel<<<32, 256>>>(w4, b4);

    // L4: 64 -> 512 on h1 (HMMA, per-batch bias, glob folded, weight rows offset 32)
    hmma_gemm_kernel<<<dim3(8, 2048), blk, SMEM>>>(w4 + 32, 96, bias4p, 1, y1, 64, 0, y4, 512);
    finalize3_kernel<<<512, 256>>>(g4, be4, 3);

    // L5: 512 -> 256 (HMMA)
    hmma_gemm_kernel<<<dim3(4, 2048), blk, SMEM>>>(w5, 512, b5, 0, y4, 512, 3, y5, 256);
    finalize3_kernel<<<256, 256>>>(g5, be5, 4);

    // L6: 256 -> 128 (HMMA)
    hmma_gemm_kernel<<<dim3(2, 2048), blk, SMEM>>>(w6, 256, b6, 0, y5, 256, 4, y6, 128);
    finalize3_kernel<<<128, 256>>>(g6, be6, 5);

    // L7: 128 -> 3, tanh, dedicated kernel, straight to output
    conv7_kernel<<<BNTOT/4/256, blk>>>(w7, b7, y6, (float*)d_out);
}